// round 5
// baseline (speedup 1.0000x reference)
#include <cuda_runtime.h>

constexpr int C = 128;
constexpr int H = 8;

// ---------------- device scratch (no allocation) ----------------
__device__ float g_WkT[H][C][C];   // [h][i][o]
__device__ float g_WqT[H][C][C];   // [h][i][o]
__device__ float g_WvT[H][C][C];   // [h][i][d]
__device__ float g_T1 [H][C][C];   // phi(K)^T * S : [h][m][i]
__device__ float g_kss[H][C];      // sum_n phi_ks : [h][m]
__device__ float g_ktv[H][C][C];   // [h][m][d]
__device__ float g_Wva[C][C];      // mean_h Wv : [d][i]
__device__ float g_bva[C];
__device__ float g_MT [C][C];      // (v_map_w * Wv_avg)^T : [i][o]
__device__ float g_c  [C];

#define SMEM_K1 ((16384 + 8192 + 64*132 + 64) * 4)
#define SMEM_K2 ((8192 + 16384) * 4)
#define SMEM_K3 ((8192 + 16384 + 64*132 + 64 + 64 + 128) * 4)
#define SMEM_P2 ((128*129 + 128*33) * 4)

// =========================================================================
// Prep 1: weight transposes, Wv average, zero accumulators. 33 blocks x 256.
// =========================================================================
__global__ void k_prep1(const float* __restrict__ Wq, const float* __restrict__ Wk,
                        const float* __restrict__ Wv, const float* __restrict__ Wvb) {
    int b = blockIdx.x, t = threadIdx.x;
    if (b < 24) {
        const float* src; float* dst;
        if (b < 8)       { src = Wk + b*C*C;      dst = &g_WkT[b][0][0]; }
        else if (b < 16) { src = Wq + (b-8)*C*C;  dst = &g_WqT[b-8][0][0]; }
        else             { src = Wv + (b-16)*C*C; dst = &g_WvT[b-16][0][0]; }
        #pragma unroll
        for (int it = 0; it < 16; it++) {
            int f = t + 256*it;
            int o = f >> 5, i = (f & 31) * 4;
            float4 v = *(const float4*)(src + o*C + i);
            dst[(i+0)*C + o] = v.x;
            dst[(i+1)*C + o] = v.y;
            dst[(i+2)*C + o] = v.z;
            dst[(i+3)*C + o] = v.w;
        }
    } else if (b == 24) {
        for (int it = 0; it < 64; it++) {
            int idx = t + 256*it;
            float a = 0.f;
            #pragma unroll
            for (int h = 0; h < H; h++) a += Wv[h*C*C + idx];
            (&g_Wva[0][0])[idx] = a * 0.125f;
        }
        if (t < C) {
            float a = 0.f;
            #pragma unroll
            for (int h = 0; h < H; h++) a += Wvb[h*C + t];
            g_bva[t] = a * 0.125f;
        }
    } else {
        int zb = b - 25;  // 0..7
        float4* T4 = (float4*)&g_T1[0][0][0];
        #pragma unroll
        for (int it = 0; it < 16; it++)
            T4[zb*256 + t + 2048*it] = make_float4(0.f, 0.f, 0.f, 0.f);
        if (zb == 0)
            ((float4*)&g_kss[0][0])[t] = make_float4(0.f, 0.f, 0.f, 0.f);
    }
}

// =========================================================================
// Prep 2: M^T = (v_map_w * Wv_avg)^T and c. 4 blocks x 256, smem SMEM_P2.
// =========================================================================
__global__ void k_prep2(const float* __restrict__ vmw, const float* __restrict__ vmb) {
    extern __shared__ float sm[];
    float* VS = sm;             // [128][129]  vmw
    float* AS = VS + 128*129;   // [128][33]   Wva slice
    int b = blockIdx.x, t = threadIdx.x;
    int i0 = b * 32;
    #pragma unroll
    for (int it = 0; it < 16; it++) {
        int f = t + 256*it; int o = f >> 5, d4 = (f & 31) * 4;
        float4 v = *(const float4*)(vmw + o*C + d4);
        VS[o*129 + d4+0] = v.x; VS[o*129 + d4+1] = v.y;
        VS[o*129 + d4+2] = v.z; VS[o*129 + d4+3] = v.w;
    }
    #pragma unroll
    for (int it = 0; it < 16; it++) {
        int f = t + 256*it;
        int d = f >> 5, ii = f & 31;
        AS[d*33 + ii] = g_Wva[d][i0 + ii];
    }
    __syncthreads();
    int il = (t >> 4) * 2, o0 = (t & 15) * 8;
    float acc[2][8];
    #pragma unroll
    for (int i = 0; i < 2; i++)
        #pragma unroll
        for (int j = 0; j < 8; j++) acc[i][j] = 0.f;
    for (int d = 0; d < C; d++) {
        float a0 = AS[d*33 + il], a1 = AS[d*33 + il + 1];
        #pragma unroll
        for (int j = 0; j < 8; j++) {
            float bv = VS[(o0+j)*129 + d];
            acc[0][j] = fmaf(a0, bv, acc[0][j]);
            acc[1][j] = fmaf(a1, bv, acc[1][j]);
        }
    }
    #pragma unroll
    for (int i = 0; i < 2; i++)
        #pragma unroll
        for (int j = 0; j < 8; j++)
            g_MT[i0 + il + i][o0 + j] = acc[i][j];
    if (b == 0) {
        __syncthreads();
        if (t < C) {
            float a = 0.f;
            for (int d = 0; d < C; d++) a = fmaf(VS[t*129 + d], g_bva[d], a);
            g_c[t] = a + vmb[t];
        }
    }
}

// ---- 64xC tile GEMM: X += A(64 x 128, stride astride) * B(128 x 128, k-major) ----
__device__ __forceinline__ void gemm_tile(const float* __restrict__ A,
                                          const float* __restrict__ B,
                                          int ty, int tx, float x[8][4], int astride) {
    for (int k4 = 0; k4 < 32; k4++) {
        float4 a[8];
        #pragma unroll
        for (int i = 0; i < 8; i++)
            a[i] = *(const float4*)&A[(ty*8 + i)*astride + k4*4];
        #pragma unroll
        for (int kk = 0; kk < 4; kk++) {
            float4 bv = *(const float4*)&B[(k4*4 + kk)*C + tx*4];
            #pragma unroll
            for (int i = 0; i < 8; i++) {
                float av = (kk == 0) ? a[i].x : (kk == 1) ? a[i].y
                          : (kk == 2) ? a[i].z : a[i].w;
                x[i][0] = fmaf(av, bv.x, x[i][0]);
                x[i][1] = fmaf(av, bv.y, x[i][1]);
                x[i][2] = fmaf(av, bv.z, x[i][2]);
                x[i][3] = fmaf(av, bv.w, x[i][3]);
            }
        }
    }
}

// =========================================================================
// Phase 1: T1[h] += phi(ks)^T * S ; kss[h] += sum_n phi(ks).
// grid = dim3(18, 8), 256 threads, dynamic smem SMEM_K1.
// =========================================================================
__global__ __launch_bounds__(256, 1) void k_phase1(const float* __restrict__ src,
                                                   const float* __restrict__ Wkb,
                                                   const float* __restrict__ nsc,
                                                   int nchunks) {
    extern __shared__ float sm[];
    float* W  = sm;            // 128*128 WkT
    float* S  = W + 16384;     // 64*128 source rows
    float* P  = S + 8192;      // 64*132 phi buffer
    float* RS = P + 64*132;    // 64 row scales
    int t = threadIdx.x;
    int h = blockIdx.y, slice = blockIdx.x;
    int ty = t >> 5, tx = t & 31;
    int rr = t >> 2, g = t & 3;
    int m0 = (t >> 4) << 3, i0 = (t & 15) << 3;
    float inv = 1.f / (fabsf(*nsc) + 1e-6f);
    float4 bias = *(const float4*)(Wkb + h*C + tx*4);

    #pragma unroll
    for (int it = 0; it < 16; it++)
        ((float4*)W)[t + 256*it] = ((const float4*)&g_WkT[h][0][0])[t + 256*it];

    float t1acc[8][8];
    #pragma unroll
    for (int i = 0; i < 8; i++)
        #pragma unroll
        for (int j = 0; j < 8; j++) t1acc[i][j] = 0.f;
    float kacc = 0.f;

    for (int ch = slice; ch < nchunks; ch += 18) {
        __syncthreads();   // W ready (1st iter); S,P free (later iters)
        const float4* sp = (const float4*)(src + (size_t)ch*64*C);
        #pragma unroll
        for (int it = 0; it < 8; it++)
            ((float4*)S)[t + 256*it] = sp[t + 256*it];
        __syncthreads();

        float x[8][4];
        #pragma unroll
        for (int i = 0; i < 8; i++)
            #pragma unroll
            for (int j = 0; j < 4; j++) x[i][j] = 0.f;
        gemm_tile(S, W, ty, tx, x, C);

        #pragma unroll
        for (int i = 0; i < 8; i++) {
            float4 p4; float v;
            v = fmaxf(x[i][0] + bias.x, 0.f); v = (v + 1e-6f) * inv; p4.x = v*v;
            v = fmaxf(x[i][1] + bias.y, 0.f); v = (v + 1e-6f) * inv; p4.y = v*v;
            v = fmaxf(x[i][2] + bias.z, 0.f); v = (v + 1e-6f) * inv; p4.z = v*v;
            v = fmaxf(x[i][3] + bias.w, 0.f); v = (v + 1e-6f) * inv; p4.w = v*v;
            *(float4*)&P[(ty*8 + i)*132 + tx*4] = p4;
        }
        __syncthreads();

        float s1 = 0.f, s2 = 0.f;
        #pragma unroll
        for (int cc = 0; cc < 32; cc++) {
            float pv = P[rr*132 + g + 4*cc];
            s1 += pv; s2 = fmaf(pv, pv, s2);
        }
        s1 += __shfl_xor_sync(0xffffffffu, s1, 1);
        s2 += __shfl_xor_sync(0xffffffffu, s2, 1);
        s1 += __shfl_xor_sync(0xffffffffu, s1, 2);
        s2 += __shfl_xor_sync(0xffffffffu, s2, 2);
        if (g == 0) RS[rr] = sqrtf(s1) / (sqrtf(s2) + 1e-8f);
        __syncthreads();
        float sc = RS[rr];
        #pragma unroll
        for (int cc = 0; cc < 32; cc++) P[rr*132 + g + 4*cc] *= sc;
        __syncthreads();

        if (t < C) {
            float a = 0.f;
            #pragma unroll
            for (int rw = 0; rw < 64; rw++) a += P[rw*132 + t];
            kacc += a;
        }
        for (int rw = 0; rw < 64; rw++) {
            float4 a0 = *(const float4*)&P[rw*132 + m0];
            float4 a1 = *(const float4*)&P[rw*132 + m0 + 4];
            float4 b0 = *(const float4*)&S[rw*C + i0];
            float4 b1 = *(const float4*)&S[rw*C + i0 + 4];
            float av[8] = {a0.x,a0.y,a0.z,a0.w,a1.x,a1.y,a1.z,a1.w};
            float bv[8] = {b0.x,b0.y,b0.z,b0.w,b1.x,b1.y,b1.z,b1.w};
            #pragma unroll
            for (int i = 0; i < 8; i++)
                #pragma unroll
                for (int j = 0; j < 8; j++)
                    t1acc[i][j] = fmaf(av[i], bv[j], t1acc[i][j]);
        }
    }
    #pragma unroll
    for (int i = 0; i < 8; i++)
        #pragma unroll
        for (int j = 0; j < 8; j++)
            atomicAdd(&g_T1[h][m0 + i][i0 + j], t1acc[i][j]);
    if (t < C) atomicAdd(&g_kss[h][t], kacc);
}

// =========================================================================
// K2: ktv[h] = T1[h] * Wv_h^T + kss_h (x) Wv_b_h. 16 blocks x 256, SMEM_K2.
// =========================================================================
__global__ __launch_bounds__(256, 1) void k_ktv(const float* __restrict__ Wvb) {
    extern __shared__ float sm[];
    float* T = sm;           // 64*128
    float* W = T + 8192;     // 128*128 WvT
    int b = blockIdx.x;
    int h = b >> 1, half = b & 1;
    int t = threadIdx.x, ty = t >> 5, tx = t & 31;
    #pragma unroll
    for (int it = 0; it < 8; it++)
        ((float4*)T)[t + 256*it] = ((const float4*)&g_T1[h][half*64][0])[t + 256*it];
    #pragma unroll
    for (int it = 0; it < 16; it++)
        ((float4*)W)[t + 256*it] = ((const float4*)&g_WvT[h][0][0])[t + 256*it];
    __syncthreads();
    float x[8][4];
    #pragma unroll
    for (int i = 0; i < 8; i++)
        #pragma unroll
        for (int j = 0; j < 4; j++) x[i][j] = 0.f;
    gemm_tile(T, W, ty, tx, x, C);
    float4 bb = *(const float4*)(Wvb + h*C + tx*4);
    #pragma unroll
    for (int i = 0; i < 8; i++) {
        int m = half*64 + ty*8 + i;
        float ks = g_kss[h][m];
        float4 o;
        o.x = fmaf(ks, bb.x, x[i][0]);
        o.y = fmaf(ks, bb.y, x[i][1]);
        o.z = fmaf(ks, bb.z, x[i][2]);
        o.w = fmaf(ks, bb.w, x[i][3]);
        *(float4*)&g_ktv[h][m][tx*4] = o;
    }
}

// =========================================================================
// Phase 2: attention + vss + heads mean + Lorentz time. N/64 blocks, SMEM_K3.
// =========================================================================
__global__ __launch_bounds__(256, 1) void k_phase2(const float* __restrict__ qin,
                                                   const float* __restrict__ sin_,
                                                   const float* __restrict__ Wqb,
                                                   const float* __restrict__ nsc,
                                                   float* __restrict__ out) {
    extern __shared__ float sm[];
    float* IN = sm;             // 64*128
    float* W  = IN + 8192;      // 128*128
    float* P  = W + 16384;      // 64*132
    float* WR = P + 64*132;     // 64 row weights
    float* TS = WR + 64;        // 64 time coords
    float* KS = TS + 64;        // 128 kss[h]
    int t = threadIdx.x, ty = t >> 5, tx = t & 31;
    int rr = t >> 2, g = t & 3;
    int r0 = blockIdx.x * 64;
    float inv = 1.f / (fabsf(*nsc) + 1e-6f);

    // ---- vss mean: acc = S * M^T + c ----
    #pragma unroll
    for (int it = 0; it < 8; it++)
        ((float4*)IN)[t + 256*it] = ((const float4*)(sin_ + (size_t)r0*C))[t + 256*it];
    #pragma unroll
    for (int it = 0; it < 16; it++)
        ((float4*)W)[t + 256*it] = ((const float4*)&g_MT[0][0])[t + 256*it];
    __syncthreads();
    float4 creg = ((const float4*)g_c)[tx];
    float acc[8][4];
    #pragma unroll
    for (int i = 0; i < 8; i++) {
        acc[i][0] = creg.x; acc[i][1] = creg.y; acc[i][2] = creg.z; acc[i][3] = creg.w;
    }
    gemm_tile(IN, W, ty, tx, acc, C);
    __syncthreads();

    // ---- query rows ----
    #pragma unroll
    for (int it = 0; it < 8; it++)
        ((float4*)IN)[t + 256*it] = ((const float4*)(qin + (size_t)r0*C))[t + 256*it];

    for (int h = 0; h < H; h++) {
        __syncthreads();   // IN ready (h=0); W/P free (later heads)
        #pragma unroll
        for (int it = 0; it < 16; it++)
            ((float4*)W)[t + 256*it] = ((const float4*)&g_WqT[h][0][0])[t + 256*it];
        if (t < 32) ((float4*)KS)[t] = ((const float4*)&g_kss[h][0])[t];
        float4 qb = *(const float4*)(Wqb + h*C + tx*4);
        __syncthreads();

        float x[8][4];
        #pragma unroll
        for (int i = 0; i < 8; i++)
            #pragma unroll
            for (int j = 0; j < 4; j++) x[i][j] = 0.f;
        gemm_tile(IN, W, ty, tx, x, C);

        #pragma unroll
        for (int i = 0; i < 8; i++) {
            float4 p4; float v;
            v = fmaxf(x[i][0] + qb.x, 0.f); v = (v + 1e-6f) * inv; p4.x = v*v;
            v = fmaxf(x[i][1] + qb.y, 0.f); v = (v + 1e-6f) * inv; p4.y = v*v;
            v = fmaxf(x[i][2] + qb.z, 0.f); v = (v + 1e-6f) * inv; p4.z = v*v;
            v = fmaxf(x[i][3] + qb.w, 0.f); v = (v + 1e-6f) * inv; p4.w = v*v;
            *(float4*)&P[(ty*8 + i)*132 + tx*4] = p4;
        }
        __syncthreads();

        float s1 = 0.f, s2 = 0.f, s3 = 0.f;
        #pragma unroll
        for (int cc = 0; cc < 32; cc++) {
            float pv = P[rr*132 + g + 4*cc];
            float kv = KS[g + 4*cc];
            s1 += pv; s2 = fmaf(pv, pv, s2); s3 = fmaf(pv, kv, s3);
        }
        s1 += __shfl_xor_sync(0xffffffffu, s1, 1);
        s2 += __shfl_xor_sync(0xffffffffu, s2, 1);
        s3 += __shfl_xor_sync(0xffffffffu, s3, 1);
        s1 += __shfl_xor_sync(0xffffffffu, s1, 2);
        s2 += __shfl_xor_sync(0xffffffffu, s2, 2);
        s3 += __shfl_xor_sync(0xffffffffu, s3, 2);
        if (g == 0) {
            float scv = sqrtf(s1) / (sqrtf(s2) + 1e-8f);
            WR[rr] = scv / (8.f * fmaf(scv, s3, 1e-6f));
        }
        #pragma unroll
        for (int it = 0; it < 16; it++)
            ((float4*)W)[t + 256*it] = ((const float4*)&g_ktv[h][0][0])[t + 256*it];
        __syncthreads();

        float wrow[8];
        #pragma unroll
        for (int i = 0; i < 8; i++) wrow[i] = WR[ty*8 + i];
        float num[8][4];
        #pragma unroll
        for (int i = 0; i < 8; i++)
            #pragma unroll
            for (int j = 0; j < 4; j++) num[i][j] = 0.f;
        gemm_tile(P, W, ty, tx, num, 132);
        #pragma unroll
        for (int i = 0; i < 8; i++)
            #pragma unroll
            for (int j = 0; j < 4; j++)
                acc[i][j] = fmaf(wrow[i], num[i][j], acc[i][j]);
    }

    // ---- Lorentz time coordinate + store ----
    __syncthreads();
    #pragma unroll
    for (int i = 0; i < 8; i++)
        *(float4*)&P[(ty*8 + i)*132 + tx*4] =
            make_float4(acc[i][0], acc[i][1], acc[i][2], acc[i][3]);
    __syncthreads();
    float ssq = 0.f;
    #pragma unroll
    for (int cc = 0; cc < 32; cc++) {
        float pv = P[rr*132 + g + 4*cc];
        ssq = fmaf(pv, pv, ssq);
    }
    ssq += __shfl_xor_sync(0xffffffffu, ssq, 1);
    ssq += __shfl_xor_sync(0xffffffffu, ssq, 2);
    if (g == 0) TS[rr] = sqrtf(ssq + 1.0f);
    __syncthreads();
    #pragma unroll
    for (int i = 0; i < 8; i++) {
        int row = r0 + ty*8 + i;
        float* op = out + (size_t)row * 129;
        op[1 + tx*4 + 0] = acc[i][0];
        op[1 + tx*4 + 1] = acc[i][1];
        op[1 + tx*4 + 2] = acc[i][2];
        op[1 + tx*4 + 3] = acc[i][3];
        if (tx == 0) op[0] = TS[ty*8 + i];
    }
}

// =========================================================================
extern "C" void kernel_launch(void* const* d_in, const int* in_sizes, int n_in,
                              void* d_out, int out_size) {
    const float* qin = (const float*)d_in[0];
    const float* sin_ = (const float*)d_in[1];
    const float* Wq  = (const float*)d_in[2];
    const float* Wqb = (const float*)d_in[3];
    const float* Wk  = (const float*)d_in[4];
    const float* Wkb = (const float*)d_in[5];
    const float* Wv  = (const float*)d_in[6];
    const float* Wvb = (const float*)d_in[7];
    const float* vmw = (const float*)d_in[8];
    const float* vmb = (const float*)d_in[9];
    const float* nsc = (const float*)d_in[10];
    float* out = (float*)d_out;
    int N = in_sizes[0] / C;
    int nchunks = N / 64;

    cudaFuncSetAttribute(k_prep2,  cudaFuncAttributeMaxDynamicSharedMemorySize, SMEM_P2);
    cudaFuncSetAttribute(k_phase1, cudaFuncAttributeMaxDynamicSharedMemorySize, SMEM_K1);
    cudaFuncSetAttribute(k_ktv,    cudaFuncAttributeMaxDynamicSharedMemorySize, SMEM_K2);
    cudaFuncSetAttribute(k_phase2, cudaFuncAttributeMaxDynamicSharedMemorySize, SMEM_K3);

    k_prep1<<<33, 256>>>(Wq, Wk, Wv, Wvb);
    k_prep2<<<4, 256, SMEM_P2>>>(vmw, vmb);
    k_phase1<<<dim3(18, H), 256, SMEM_K1>>>(sin_, Wkb, nsc, nchunks);
    k_ktv<<<16, 256, SMEM_K2>>>(Wvb);
    k_phase2<<<nchunks, 256, SMEM_K3>>>(qin, sin_, Wqb, nsc, out);
}

// round 8
// speedup vs baseline: 1.2519x; 1.2519x over previous
#include <cuda_runtime.h>
#include <cuda_bf16.h>
#include <cstdint>

constexpr int C = 128;
constexpr int H = 8;

// ---------------- device scratch (no allocation) ----------------
__device__ float g_WkT[H][C][C];            // [h][i][o] fp32 (phase1)
__device__ float g_WvT[H][C][C];            // [h][i][d] fp32 (k_ktv)
__device__ float g_T1 [H][C][C];            // phi(K)^T * S : [h][m][i]
__device__ float g_kss[H][C];               // sum_n phi_ks
__device__ float g_c  [C];                  // v_map bias term
__device__ float g_bva[C];
__device__ float g_Wva[C][C];               // mean_h Wv : [d][i]
__device__ __nv_bfloat16 g_Wq_h[H][C][C];   // [i][o] bf16 hi
__device__ __nv_bfloat16 g_Wq_l[H][C][C];   // [i][o] bf16 lo
__device__ __nv_bfloat16 g_M_h[C][C];       // [i][o]
__device__ __nv_bfloat16 g_M_l[C][C];
__device__ __nv_bfloat16 g_ktv_h[H][C][C];  // [m][d]
__device__ __nv_bfloat16 g_ktv_l[H][C][C];

#define SMEM_K1 ((16384 + 8192 + 64*132 + 64) * 4)
#define SMEM_K2 ((8192 + 16384) * 4)
#define SMEM_P2 ((128*129 + 128*33) * 4)
// phase2: Qh,Ql,Ah,Al (64x136 halves each) + Bh,Bl (128x136 halves each)
//         + Xs (64x132 f32) + QB(128) + KS(128) + WR(64) + TS(64)
#define SMEM_K3 (4*64*136*2 + 2*128*136*2 + 64*132*4 + (128+128+64+64)*4)

// ---------------- bf16 split helpers ----------------
__device__ __forceinline__ void bf16_split(float v, __nv_bfloat16& hi, __nv_bfloat16& lo) {
    hi = __float2bfloat16_rn(v);
    lo = __float2bfloat16_rn(v - __bfloat162float(hi));
}

// =========================================================================
// Prep 1: Wk/Wv transposes (fp32), Wq -> bf16 [i][o] planes, Wv average,
// zero accumulators. 33 blocks x 256.
// =========================================================================
__global__ void k_prep1(const float* __restrict__ Wq, const float* __restrict__ Wk,
                        const float* __restrict__ Wv, const float* __restrict__ Wvb) {
    int b = blockIdx.x, t = threadIdx.x;
    if (b < 8 || (b >= 16 && b < 24)) {
        const float* src; float* dst;
        if (b < 8) { src = Wk + b*C*C; dst = &g_WkT[b][0][0]; }
        else       { src = Wv + (b-16)*C*C; dst = &g_WvT[b-16][0][0]; }
        #pragma unroll
        for (int it = 0; it < 16; it++) {
            int f = t + 256*it;
            int o = f >> 5, i = (f & 31) * 4;
            float4 v = *(const float4*)(src + o*C + i);
            dst[(i+0)*C + o] = v.x;
            dst[(i+1)*C + o] = v.y;
            dst[(i+2)*C + o] = v.z;
            dst[(i+3)*C + o] = v.w;
        }
    } else if (b < 16) {
        int h = b - 8;
        const float* src = Wq + h*C*C;
        __nv_bfloat16* dh = &g_Wq_h[h][0][0];
        __nv_bfloat16* dl = &g_Wq_l[h][0][0];
        #pragma unroll
        for (int it = 0; it < 16; it++) {
            int f = t + 256*it;
            int o = f >> 5, i = (f & 31) * 4;
            float4 v = *(const float4*)(src + o*C + i);
            float vv[4] = {v.x, v.y, v.z, v.w};
            #pragma unroll
            for (int k = 0; k < 4; k++) {
                __nv_bfloat16 hi, lo;
                bf16_split(vv[k], hi, lo);
                dh[(i+k)*C + o] = hi;
                dl[(i+k)*C + o] = lo;
            }
        }
    } else if (b == 24) {
        for (int it = 0; it < 64; it++) {
            int idx = t + 256*it;
            float a = 0.f;
            #pragma unroll
            for (int h = 0; h < H; h++) a += Wv[h*C*C + idx];
            (&g_Wva[0][0])[idx] = a * 0.125f;
        }
        if (t < C) {
            float a = 0.f;
            #pragma unroll
            for (int h = 0; h < H; h++) a += Wvb[h*C + t];
            g_bva[t] = a * 0.125f;
        }
    } else {
        int zb = b - 25;  // 0..7
        float4* T4 = (float4*)&g_T1[0][0][0];
        #pragma unroll
        for (int it = 0; it < 16; it++)
            T4[zb*256 + t + 2048*it] = make_float4(0.f, 0.f, 0.f, 0.f);
        if (zb == 0)
            ((float4*)&g_kss[0][0])[t] = make_float4(0.f, 0.f, 0.f, 0.f);
    }
}

// =========================================================================
// Prep 2: M = v_map_w * Wv_avg as bf16 [i][o] planes; c vector. 4 blocks.
// =========================================================================
__global__ void k_prep2(const float* __restrict__ vmw, const float* __restrict__ vmb) {
    extern __shared__ float sm[];
    float* VS = sm;             // [128][129] vmw
    float* AS = VS + 128*129;   // [128][33]  Wva slice
    int b = blockIdx.x, t = threadIdx.x;
    int i0 = b * 32;
    #pragma unroll
    for (int it = 0; it < 16; it++) {
        int f = t + 256*it; int o = f >> 5, d4 = (f & 31) * 4;
        float4 v = *(const float4*)(vmw + o*C + d4);
        VS[o*129 + d4+0] = v.x; VS[o*129 + d4+1] = v.y;
        VS[o*129 + d4+2] = v.z; VS[o*129 + d4+3] = v.w;
    }
    #pragma unroll
    for (int it = 0; it < 16; it++) {
        int f = t + 256*it;
        int d = f >> 5, ii = f & 31;
        AS[d*33 + ii] = g_Wva[d][i0 + ii];
    }
    __syncthreads();
    int il = (t >> 4) * 2, o0 = (t & 15) * 8;
    float acc[2][8];
    #pragma unroll
    for (int i = 0; i < 2; i++)
        #pragma unroll
        for (int j = 0; j < 8; j++) acc[i][j] = 0.f;
    for (int d = 0; d < C; d++) {
        float a0 = AS[d*33 + il], a1 = AS[d*33 + il + 1];
        #pragma unroll
        for (int j = 0; j < 8; j++) {
            float bv = VS[(o0+j)*129 + d];
            acc[0][j] = fmaf(a0, bv, acc[0][j]);
            acc[1][j] = fmaf(a1, bv, acc[1][j]);
        }
    }
    #pragma unroll
    for (int i = 0; i < 2; i++)
        #pragma unroll
        for (int j = 0; j < 8; j++) {
            __nv_bfloat16 hi, lo;
            bf16_split(acc[i][j], hi, lo);
            g_M_h[i0 + il + i][o0 + j] = hi;
            g_M_l[i0 + il + i][o0 + j] = lo;
        }
    if (b == 0) {
        __syncthreads();
        if (t < C) {
            float a = 0.f;
            for (int d = 0; d < C; d++) a = fmaf(VS[t*129 + d], g_bva[d], a);
            g_c[t] = a + vmb[t];
        }
    }
}

// ---- fp32 tile GEMM (phase1/k_ktv): X += A(64x128) * B(128x128 k-major) ----
__device__ __forceinline__ void gemm_tile(const float* __restrict__ A,
                                          const float* __restrict__ B,
                                          int ty, int tx, float x[8][4], int astride) {
    for (int k4 = 0; k4 < 32; k4++) {
        float4 a[8];
        #pragma unroll
        for (int i = 0; i < 8; i++)
            a[i] = *(const float4*)&A[(ty*8 + i)*astride + k4*4];
        #pragma unroll
        for (int kk = 0; kk < 4; kk++) {
            float4 bv = *(const float4*)&B[(k4*4 + kk)*C + tx*4];
            #pragma unroll
            for (int i = 0; i < 8; i++) {
                float av = (kk == 0) ? a[i].x : (kk == 1) ? a[i].y
                          : (kk == 2) ? a[i].z : a[i].w;
                x[i][0] = fmaf(av, bv.x, x[i][0]);
                x[i][1] = fmaf(av, bv.y, x[i][1]);
                x[i][2] = fmaf(av, bv.z, x[i][2]);
                x[i][3] = fmaf(av, bv.w, x[i][3]);
            }
        }
    }
}

// =========================================================================
// Phase 1: T1[h] += phi(ks)^T * S ; kss[h] += sum_n phi(ks).  (fp32)
// grid = dim3(18, 8), 256 threads, smem SMEM_K1.
// =========================================================================
__global__ __launch_bounds__(256, 1) void k_phase1(const float* __restrict__ src,
                                                   const float* __restrict__ Wkb,
                                                   const float* __restrict__ nsc,
                                                   int nchunks) {
    extern __shared__ float sm[];
    float* W  = sm;            // 128*128 WkT
    float* S  = W + 16384;     // 64*128
    float* P  = S + 8192;      // 64*132
    float* RS = P + 64*132;    // 64
    int t = threadIdx.x;
    int h = blockIdx.y, slice = blockIdx.x;
    int ty = t >> 5, tx = t & 31;
    int rr = t >> 2, g = t & 3;
    int m0 = (t >> 4) << 3, i0 = (t & 15) << 3;
    float inv = 1.f / (fabsf(*nsc) + 1e-6f);
    float4 bias = *(const float4*)(Wkb + h*C + tx*4);

    #pragma unroll
    for (int it = 0; it < 16; it++)
        ((float4*)W)[t + 256*it] = ((const float4*)&g_WkT[h][0][0])[t + 256*it];

    float t1acc[8][8];
    #pragma unroll
    for (int i = 0; i < 8; i++)
        #pragma unroll
        for (int j = 0; j < 8; j++) t1acc[i][j] = 0.f;
    float kacc = 0.f;

    for (int ch = slice; ch < nchunks; ch += 18) {
        __syncthreads();
        const float4* sp = (const float4*)(src + (size_t)ch*64*C);
        #pragma unroll
        for (int it = 0; it < 8; it++)
            ((float4*)S)[t + 256*it] = sp[t + 256*it];
        __syncthreads();

        float x[8][4];
        #pragma unroll
        for (int i = 0; i < 8; i++)
            #pragma unroll
            for (int j = 0; j < 4; j++) x[i][j] = 0.f;
        gemm_tile(S, W, ty, tx, x, C);

        #pragma unroll
        for (int i = 0; i < 8; i++) {
            float4 p4; float v;
            v = fmaxf(x[i][0] + bias.x, 0.f); v = (v + 1e-6f) * inv; p4.x = v*v;
            v = fmaxf(x[i][1] + bias.y, 0.f); v = (v + 1e-6f) * inv; p4.y = v*v;
            v = fmaxf(x[i][2] + bias.z, 0.f); v = (v + 1e-6f) * inv; p4.z = v*v;
            v = fmaxf(x[i][3] + bias.w, 0.f); v = (v + 1e-6f) * inv; p4.w = v*v;
            *(float4*)&P[(ty*8 + i)*132 + tx*4] = p4;
        }
        __syncthreads();

        float s1 = 0.f, s2 = 0.f;
        #pragma unroll
        for (int cc = 0; cc < 32; cc++) {
            float pv = P[rr*132 + g + 4*cc];
            s1 += pv; s2 = fmaf(pv, pv, s2);
        }
        s1 += __shfl_xor_sync(0xffffffffu, s1, 1);
        s2 += __shfl_xor_sync(0xffffffffu, s2, 1);
        s1 += __shfl_xor_sync(0xffffffffu, s1, 2);
        s2 += __shfl_xor_sync(0xffffffffu, s2, 2);
        if (g == 0) RS[rr] = sqrtf(s1) / (sqrtf(s2) + 1e-8f);
        __syncthreads();
        float sc = RS[rr];
        #pragma unroll
        for (int cc = 0; cc < 32; cc++) P[rr*132 + g + 4*cc] *= sc;
        __syncthreads();

        if (t < C) {
            float a = 0.f;
            #pragma unroll
            for (int rw = 0; rw < 64; rw++) a += P[rw*132 + t];
            kacc += a;
        }
        for (int rw = 0; rw < 64; rw++) {
            float4 a0 = *(const float4*)&P[rw*132 + m0];
            float4 a1 = *(const float4*)&P[rw*132 + m0 + 4];
            float4 b0 = *(const float4*)&S[rw*C + i0];
            float4 b1 = *(const float4*)&S[rw*C + i0 + 4];
            float av[8] = {a0.x,a0.y,a0.z,a0.w,a1.x,a1.y,a1.z,a1.w};
            float bv[8] = {b0.x,b0.y,b0.z,b0.w,b1.x,b1.y,b1.z,b1.w};
            #pragma unroll
            for (int i = 0; i < 8; i++)
                #pragma unroll
                for (int j = 0; j < 8; j++)
                    t1acc[i][j] = fmaf(av[i], bv[j], t1acc[i][j]);
        }
    }
    #pragma unroll
    for (int i = 0; i < 8; i++)
        #pragma unroll
        for (int j = 0; j < 8; j++)
            atomicAdd(&g_T1[h][m0 + i][i0 + j], t1acc[i][j]);
    if (t < C) atomicAdd(&g_kss[h][t], kacc);
}

// =========================================================================
// K2: ktv[h] = T1[h]*Wv_h^T + kss_h (x) Wv_b_h -> bf16 hi/lo planes [m][d].
// 16 blocks x 256, SMEM_K2.
// =========================================================================
__global__ __launch_bounds__(256, 1) void k_ktv(const float* __restrict__ Wvb) {
    extern __shared__ float sm[];
    float* T = sm;           // 64*128
    float* W = T + 8192;     // 128*128 WvT
    int b = blockIdx.x;
    int h = b >> 1, half = b & 1;
    int t = threadIdx.x, ty = t >> 5, tx = t & 31;
    #pragma unroll
    for (int it = 0; it < 8; it++)
        ((float4*)T)[t + 256*it] = ((const float4*)&g_T1[h][half*64][0])[t + 256*it];
    #pragma unroll
    for (int it = 0; it < 16; it++)
        ((float4*)W)[t + 256*it] = ((const float4*)&g_WvT[h][0][0])[t + 256*it];
    __syncthreads();
    float x[8][4];
    #pragma unroll
    for (int i = 0; i < 8; i++)
        #pragma unroll
        for (int j = 0; j < 4; j++) x[i][j] = 0.f;
    gemm_tile(T, W, ty, tx, x, C);
    float4 bb = *(const float4*)(Wvb + h*C + tx*4);
    #pragma unroll
    for (int i = 0; i < 8; i++) {
        int m = half*64 + ty*8 + i;
        float ks = g_kss[h][m];
        float o[4];
        o[0] = fmaf(ks, bb.x, x[i][0]);
        o[1] = fmaf(ks, bb.y, x[i][1]);
        o[2] = fmaf(ks, bb.z, x[i][2]);
        o[3] = fmaf(ks, bb.w, x[i][3]);
        #pragma unroll
        for (int j = 0; j < 4; j++) {
            __nv_bfloat16 hi, lo;
            bf16_split(o[j], hi, lo);
            g_ktv_h[h][m][tx*4 + j] = hi;
            g_ktv_l[h][m][tx*4 + j] = lo;
        }
    }
}

// ---------------- mma.sync plumbing ----------------
__device__ __forceinline__ uint32_t smem_u32(const void* p) {
    return (uint32_t)__cvta_generic_to_shared(p);
}
__device__ __forceinline__ void ldsm4(uint32_t r[4], uint32_t addr) {
    asm volatile("ldmatrix.sync.aligned.m8n8.x4.shared.b16 {%0,%1,%2,%3}, [%4];"
        : "=r"(r[0]), "=r"(r[1]), "=r"(r[2]), "=r"(r[3]) : "r"(addr));
}
__device__ __forceinline__ void ldsm2t(uint32_t r[2], uint32_t addr) {
    asm volatile("ldmatrix.sync.aligned.m8n8.x2.trans.shared.b16 {%0,%1}, [%2];"
        : "=r"(r[0]), "=r"(r[1]) : "r"(addr));
}
__device__ __forceinline__ void mma16816(float c[4], const uint32_t a[4], const uint32_t b[2]) {
    asm volatile("mma.sync.aligned.m16n8k16.row.col.f32.bf16.bf16.f32 "
        "{%0,%1,%2,%3}, {%4,%5,%6,%7}, {%8,%9}, {%0,%1,%2,%3};"
        : "+f"(c[0]), "+f"(c[1]), "+f"(c[2]), "+f"(c[3])
        : "r"(a[0]), "r"(a[1]), "r"(a[2]), "r"(a[3]), "r"(b[0]), "r"(b[1]));
}

// 64x128 += A(64x128) * B(128x128 k-major), split-bf16 3-pass.
// warp wr = rows 16*wr..+16 ; wc = cols 64*wc..+64 (8 n-tiles).
__device__ __forceinline__ void mma_gemm64x128(
    const __nv_bfloat16* Ah, const __nv_bfloat16* Al,
    const __nv_bfloat16* Bh, const __nv_bfloat16* Bl,
    float acc[8][4], int wr, int wc, int l) {
    uint32_t aoff = (uint32_t)(((16*wr + (l & 15))*136 + ((l >> 4)*8)) * 2);
    uint32_t ah_base = smem_u32(Ah) + aoff;
    uint32_t al_base = smem_u32(Al) + aoff;
    uint32_t boff = (uint32_t)(((l & 15)*136 + 64*wc) * 2);
    uint32_t bh_base = smem_u32(Bh) + boff;
    uint32_t bl_base = smem_u32(Bl) + boff;
    #pragma unroll
    for (int kk = 0; kk < 8; kk++) {
        uint32_t a_h[4], a_l[4];
        ldsm4(a_h, ah_base + kk*32);
        ldsm4(a_l, al_base + kk*32);
        #pragma unroll
        for (int j = 0; j < 8; j++) {
            uint32_t b_h[2], b_l[2];
            ldsm2t(b_h, bh_base + kk*4352 + j*16);
            ldsm2t(b_l, bl_base + kk*4352 + j*16);
            mma16816(acc[j], a_h, b_h);
            mma16816(acc[j], a_h, b_l);
            mma16816(acc[j], a_l, b_h);
        }
    }
}

// load 64 fp32 rows -> bf16 hi/lo planes (stride 136 halves)
__device__ __forceinline__ void load_rows_bf16(const float* __restrict__ src,
                                               __nv_bfloat16* dh, __nv_bfloat16* dl, int t) {
    const float4* sp = (const float4*)src;
    #pragma unroll
    for (int it = 0; it < 8; it++) {
        int f = t + 256*it;             // 2048 float4
        int row = f >> 5, c4 = (f & 31) * 4;
        float4 v = sp[f];
        float vv[4] = {v.x, v.y, v.z, v.w};
        union { __nv_bfloat16 h[4]; uint2 u; } Hu, Lu;
        #pragma unroll
        for (int k = 0; k < 4; k++) bf16_split(vv[k], Hu.h[k], Lu.h[k]);
        *(uint2*)&dh[row*136 + c4] = Hu.u;
        *(uint2*)&dl[row*136 + c4] = Lu.u;
    }
}

// copy 128x128 bf16 global -> smem (stride 136 halves)
__device__ __forceinline__ void load_w_bf16(const __nv_bfloat16* __restrict__ src,
                                            __nv_bfloat16* dst, int t) {
    const uint4* sp = (const uint4*)src;   // 2048 uint4
    #pragma unroll
    for (int it = 0; it < 8; it++) {
        int u = t + 256*it;
        int row = u >> 4, c8 = (u & 15) * 8;
        *(uint4*)&dst[row*136 + c8] = sp[u];
    }
}

// =========================================================================
// Phase 2 (tensorized): vss + 8-head attention + heads mean + Lorentz time.
// N/64 blocks x 256 threads, smem SMEM_K3.
// =========================================================================
__global__ __launch_bounds__(256, 1) void k_phase2(const float* __restrict__ qin,
                                                   const float* __restrict__ sin_,
                                                   const float* __restrict__ Wqb,
                                                   const float* __restrict__ nsc,
                                                   float* __restrict__ out) {
    extern __shared__ char smraw[];
    __nv_bfloat16* Qh = (__nv_bfloat16*)smraw;
    __nv_bfloat16* Ql = Qh + 64*136;
    __nv_bfloat16* Ah = Ql + 64*136;
    __nv_bfloat16* Al = Ah + 64*136;
    __nv_bfloat16* Bh = Al + 64*136;
    __nv_bfloat16* Bl = Bh + 128*136;
    float* Xs = (float*)(Bl + 128*136);  // 64*132
    float* QB = Xs + 64*132;             // 128
    float* KS = QB + 128;                // 128
    float* WR = KS + 128;                // 64
    float* TS = WR + 64;                 // 64

    int t = threadIdx.x;
    int w = t >> 5, l = t & 31, wr = w >> 1, wc = w & 1;
    int rr = t >> 2, g = t & 3;
    int r0 = blockIdx.x * 64;
    float inv = 1.f / (fabsf(*nsc) + 1e-6f);
    int srow = 16*wr + (l >> 2), scol = 64*wc + 2*(l & 3);

    // ---- load Q, S (bf16 planes) and M weights ----
    load_rows_bf16(qin + (size_t)r0*C, Qh, Ql, t);
    load_rows_bf16(sin_ + (size_t)r0*C, Ah, Al, t);
    load_w_bf16(&g_M_h[0][0], Bh, t);
    load_w_bf16(&g_M_l[0][0], Bl, t);
    __syncthreads();

    // ---- acc = c + S*M^T (vss head-mean) ----
    float acc[8][4];
    #pragma unroll
    for (int j = 0; j < 8; j++) {
        float2 cv = *(const float2*)&g_c[64*wc + 8*j + 2*(l & 3)];
        acc[j][0] = cv.x; acc[j][1] = cv.y; acc[j][2] = cv.x; acc[j][3] = cv.y;
    }
    mma_gemm64x128(Ah, Al, Bh, Bl, acc, wr, wc, l);

    for (int h = 0; h < H; h++) {
        __syncthreads();  // prior mma (vss or num) done with Abuf/Bbuf
        load_w_bf16(&g_Wq_h[h][0][0], Bh, t);
        load_w_bf16(&g_Wq_l[h][0][0], Bl, t);
        if (t < 32)      ((float4*)QB)[t]    = ((const float4*)(Wqb + h*C))[t];
        else if (t < 64) ((float4*)KS)[t-32] = ((const float4*)&g_kss[h][0])[t-32];
        __syncthreads();

        // qs = Q * Wq^T
        float x[8][4];
        #pragma unroll
        for (int j = 0; j < 8; j++)
            #pragma unroll
            for (int e = 0; e < 4; e++) x[j][e] = 0.f;
        mma_gemm64x128(Qh, Ql, Bh, Bl, x, wr, wc, l);
        #pragma unroll
        for (int j = 0; j < 8; j++) {
            *(float2*)&Xs[srow*132 + scol + 8*j]     = make_float2(x[j][0], x[j][1]);
            *(float2*)&Xs[(srow+8)*132 + scol + 8*j] = make_float2(x[j][2], x[j][3]);
        }
        __syncthreads();

        // phi + row reductions; then stage ktv into B planes
        float s1 = 0.f, s2 = 0.f, s3 = 0.f;
        #pragma unroll
        for (int cc = 0; cc < 32; cc++) {
            int col = g + 4*cc;
            float xv = Xs[rr*132 + col] + QB[col];
            float v = (fmaxf(xv, 0.f) + 1e-6f) * inv;
            float p = v * v;
            Xs[rr*132 + col] = p;
            s1 += p; s2 = fmaf(p, p, s2); s3 = fmaf(p, KS[col], s3);
        }
        s1 += __shfl_xor_sync(0xffffffffu, s1, 1);
        s2 += __shfl_xor_sync(0xffffffffu, s2, 1);
        s3 += __shfl_xor_sync(0xffffffffu, s3, 1);
        s1 += __shfl_xor_sync(0xffffffffu, s1, 2);
        s2 += __shfl_xor_sync(0xffffffffu, s2, 2);
        s3 += __shfl_xor_sync(0xffffffffu, s3, 2);
        if (g == 0) {
            float scv = sqrtf(s1) / (sqrtf(s2) + 1e-8f);
            WR[rr] = scv / (8.f * fmaf(scv, s3, 1e-6f));
        }
        load_w_bf16(&g_ktv_h[h][0][0], Bh, t);
        load_w_bf16(&g_ktv_l[h][0][0], Bl, t);
        __syncthreads();

        // A = bf16(w_row * p)
        float wgt = WR[rr];
        #pragma unroll
        for (int cc = 0; cc < 32; cc++) {
            int col = g + 4*cc;
            float val = Xs[rr*132 + col] * wgt;
            __nv_bfloat16 hi, lo;
            bf16_split(val, hi, lo);
            Ah[rr*136 + col] = hi;
            Al[rr*136 + col] = lo;
        }
        __syncthreads();

        // acc += (w.p) * ktv
        mma_gemm64x128(Ah, Al, Bh, Bl, acc, wr, wc, l);
    }

    // ---- stage acc, Lorentz time coordinate, store ----
    __syncthreads();
    #pragma unroll
    for (int j = 0; j < 8; j++) {
        *(float2*)&Xs[srow*132 + scol + 8*j]     = make_float2(acc[j][0], acc[j][1]);
        *(float2*)&Xs[(srow+8)*132 + scol + 8*j] = make_float2(acc[j][2], acc[j][3]);
    }
    __syncthreads();
    float ssq = 0.f;
    #pragma unroll
    for (int cc = 0; cc < 32; cc++) {
        float pv = Xs[rr*132 + g + 4*cc];
        ssq = fmaf(pv, pv, ssq);
    }
    ssq += __shfl_xor_sync(0xffffffffu, ssq, 1);
    ssq += __shfl_xor_sync(0xffffffffu, ssq, 2);
    if (g == 0) TS[rr] = sqrtf(ssq + 1.0f);
    __syncthreads();
    {
        int row = r0 + rr;
        float* op = out + (size_t)row * 129;
        #pragma unroll
        for (int cc = 0; cc < 32; cc++) {
            int col = g + 4*cc;
            op[1 + col] = Xs[rr*132 + col];
        }
        if (g == 0) op[0] = TS[rr];
    }
}

// =========================================================================
extern "C" void kernel_launch(void* const* d_in, const int* in_sizes, int n_in,
                              void* d_out, int out_size) {
    const float* qin = (const float*)d_in[0];
    const float* sin_ = (const float*)d_in[1];
    const float* Wq  = (const float*)d_in[2];
    const float* Wqb = (const float*)d_in[3];
    const float* Wk  = (const float*)d_in[4];
    const float* Wkb = (const float*)d_in[5];
    const float* Wv  = (const float*)d_in[6];
    const float* Wvb = (const float*)d_in[7];
    const float* vmw = (const float*)d_in[8];
    const float* vmb = (const float*)d_in[9];
    const float* nsc = (const float*)d_in[10];
    float* out = (float*)d_out;
    int N = in_sizes[0] / C;
    int nchunks = N / 64;

    cudaFuncSetAttribute(k_prep2,  cudaFuncAttributeMaxDynamicSharedMemorySize, SMEM_P2);
    cudaFuncSetAttribute(k_phase1, cudaFuncAttributeMaxDynamicSharedMemorySize, SMEM_K1);
    cudaFuncSetAttribute(k_ktv,    cudaFuncAttributeMaxDynamicSharedMemorySize, SMEM_K2);
    cudaFuncSetAttribute(k_phase2, cudaFuncAttributeMaxDynamicSharedMemorySize, SMEM_K3);

    k_prep1<<<33, 256>>>(Wq, Wk, Wv, Wvb);
    k_prep2<<<4, 256, SMEM_P2>>>(vmw, vmb);
    k_phase1<<<dim3(18, H), 256, SMEM_K1>>>(sin_, Wkb, nsc, nchunks);
    k_ktv<<<16, 256, SMEM_K2>>>(Wvb);
    k_phase2<<<nchunks, 256, SMEM_K3>>>(qin, sin_, Wqb, nsc, out);
}

// round 11
// speedup vs baseline: 1.8082x; 1.4444x over previous
#include <cuda_runtime.h>
#include <cuda_bf16.h>
#include <cstdint>

constexpr int C = 128;
constexpr int H = 8;

// ---------------- device scratch (no allocation) ----------------
__device__ float g_WvT[H][C][C];            // [h][i][d] fp32 (k_ktv)
__device__ float g_T1 [H][C][C];            // phi(K)^T * S : [h][m][i]
__device__ float g_kss[H][C];               // sum_n phi_ks
__device__ float g_c  [C];                  // v_map bias term
__device__ float g_bva[C];
__device__ float g_Wva[C][C];               // mean_h Wv : [d][i]
__device__ __nv_bfloat16 g_Wq_h[H][C][C];   // [i][o] bf16 hi
__device__ __nv_bfloat16 g_Wq_l[H][C][C];   // [i][o] bf16 lo
__device__ __nv_bfloat16 g_Wk_h[H][C][C];   // [i][o] bf16 hi
__device__ __nv_bfloat16 g_Wk_l[H][C][C];   // [i][o] bf16 lo
__device__ __nv_bfloat16 g_M_h[C][C];       // [i][o]
__device__ __nv_bfloat16 g_M_l[C][C];
__device__ __nv_bfloat16 g_ktv_h[H][C][C];  // [m][d]
__device__ __nv_bfloat16 g_ktv_l[H][C][C];

// phase1: Sh,Sl,Ph,Pl (64x136) + Bh,Bl (128x136) bf16 + Xs(64x132) f32 + KB(128) + RS(64)
#define SMEM_K1 ((4*64*136 + 2*128*136) * 2 + (64*132 + 128 + 64) * 4)
#define SMEM_K2 ((8192 + 16384) * 4)
#define SMEM_P2 ((128*129 + 128*33) * 4)
// phase2: Qh,Ql,Ah,Al (64x136 halves each) + Bh,Bl (128x136 halves each)
//         + Xs (64x132 f32) + QB(128) + KS(128) + WR(64) + TS(64)
#define SMEM_K3 (4*64*136*2 + 2*128*136*2 + 64*132*4 + (128+128+64+64)*4)

// ---------------- bf16 split helpers ----------------
__device__ __forceinline__ void bf16_split(float v, __nv_bfloat16& hi, __nv_bfloat16& lo) {
    hi = __float2bfloat16_rn(v);
    lo = __float2bfloat16_rn(v - __bfloat162float(hi));
}

// =========================================================================
// Prep 1: Wk/Wq -> bf16 [i][o] planes, Wv transpose (fp32), Wv average,
// zero accumulators. 33 blocks x 256.
// =========================================================================
__global__ void k_prep1(const float* __restrict__ Wq, const float* __restrict__ Wk,
                        const float* __restrict__ Wv, const float* __restrict__ Wvb) {
    int b = blockIdx.x, t = threadIdx.x;
    if (b < 16) {
        const float* src;
        __nv_bfloat16 *dh, *dl;
        if (b < 8) { src = Wk + b*C*C;      dh = &g_Wk_h[b][0][0];   dl = &g_Wk_l[b][0][0]; }
        else       { src = Wq + (b-8)*C*C;  dh = &g_Wq_h[b-8][0][0]; dl = &g_Wq_l[b-8][0][0]; }
        #pragma unroll
        for (int it = 0; it < 16; it++) {
            int f = t + 256*it;
            int o = f >> 5, i = (f & 31) * 4;
            float4 v = *(const float4*)(src + o*C + i);
            float vv[4] = {v.x, v.y, v.z, v.w};
            #pragma unroll
            for (int k = 0; k < 4; k++) {
                __nv_bfloat16 hi, lo;
                bf16_split(vv[k], hi, lo);
                dh[(i+k)*C + o] = hi;
                dl[(i+k)*C + o] = lo;
            }
        }
    } else if (b < 24) {
        const float* src = Wv + (b-16)*C*C;
        float* dst = &g_WvT[b-16][0][0];
        #pragma unroll
        for (int it = 0; it < 16; it++) {
            int f = t + 256*it;
            int o = f >> 5, i = (f & 31) * 4;
            float4 v = *(const float4*)(src + o*C + i);
            dst[(i+0)*C + o] = v.x;
            dst[(i+1)*C + o] = v.y;
            dst[(i+2)*C + o] = v.z;
            dst[(i+3)*C + o] = v.w;
        }
    } else if (b == 24) {
        for (int it = 0; it < 64; it++) {
            int idx = t + 256*it;
            float a = 0.f;
            #pragma unroll
            for (int h = 0; h < H; h++) a += Wv[h*C*C + idx];
            (&g_Wva[0][0])[idx] = a * 0.125f;
        }
        if (t < C) {
            float a = 0.f;
            #pragma unroll
            for (int h = 0; h < H; h++) a += Wvb[h*C + t];
            g_bva[t] = a * 0.125f;
        }
    } else {
        int zb = b - 25;  // 0..7
        float4* T4 = (float4*)&g_T1[0][0][0];
        #pragma unroll
        for (int it = 0; it < 16; it++)
            T4[zb*256 + t + 2048*it] = make_float4(0.f, 0.f, 0.f, 0.f);
        if (zb == 0)
            ((float4*)&g_kss[0][0])[t] = make_float4(0.f, 0.f, 0.f, 0.f);
    }
}

// =========================================================================
// Prep 2: M = v_map_w * Wv_avg as bf16 [i][o] planes; c vector. 4 blocks.
// =========================================================================
__global__ void k_prep2(const float* __restrict__ vmw, const float* __restrict__ vmb) {
    extern __shared__ float sm[];
    float* VS = sm;             // [128][129] vmw
    float* AS = VS + 128*129;   // [128][33]  Wva slice
    int b = blockIdx.x, t = threadIdx.x;
    int i0 = b * 32;
    #pragma unroll
    for (int it = 0; it < 16; it++) {
        int f = t + 256*it; int o = f >> 5, d4 = (f & 31) * 4;
        float4 v = *(const float4*)(vmw + o*C + d4);
        VS[o*129 + d4+0] = v.x; VS[o*129 + d4+1] = v.y;
        VS[o*129 + d4+2] = v.z; VS[o*129 + d4+3] = v.w;
    }
    #pragma unroll
    for (int it = 0; it < 16; it++) {
        int f = t + 256*it;
        int d = f >> 5, ii = f & 31;
        AS[d*33 + ii] = g_Wva[d][i0 + ii];
    }
    __syncthreads();
    int il = (t >> 4) * 2, o0 = (t & 15) * 8;
    float acc[2][8];
    #pragma unroll
    for (int i = 0; i < 2; i++)
        #pragma unroll
        for (int j = 0; j < 8; j++) acc[i][j] = 0.f;
    for (int d = 0; d < C; d++) {
        float a0 = AS[d*33 + il], a1 = AS[d*33 + il + 1];
        #pragma unroll
        for (int j = 0; j < 8; j++) {
            float bv = VS[(o0+j)*129 + d];
            acc[0][j] = fmaf(a0, bv, acc[0][j]);
            acc[1][j] = fmaf(a1, bv, acc[1][j]);
        }
    }
    #pragma unroll
    for (int i = 0; i < 2; i++)
        #pragma unroll
        for (int j = 0; j < 8; j++) {
            __nv_bfloat16 hi, lo;
            bf16_split(acc[i][j], hi, lo);
            g_M_h[i0 + il + i][o0 + j] = hi;
            g_M_l[i0 + il + i][o0 + j] = lo;
        }
    if (b == 0) {
        __syncthreads();
        if (t < C) {
            float a = 0.f;
            for (int d = 0; d < C; d++) a = fmaf(VS[t*129 + d], g_bva[d], a);
            g_c[t] = a + vmb[t];
        }
    }
}

// ---- fp32 tile GEMM (k_ktv): X += A(64 x 128) * B(128 x 128, k-major) ----
__device__ __forceinline__ void gemm_tile(const float* __restrict__ A,
                                          const float* __restrict__ B,
                                          int ty, int tx, float x[8][4], int astride) {
    for (int k4 = 0; k4 < 32; k4++) {
        float4 a[8];
        #pragma unroll
        for (int i = 0; i < 8; i++)
            a[i] = *(const float4*)&A[(ty*8 + i)*astride + k4*4];
        #pragma unroll
        for (int kk = 0; kk < 4; kk++) {
            float4 bv = *(const float4*)&B[(k4*4 + kk)*C + tx*4];
            #pragma unroll
            for (int i = 0; i < 8; i++) {
                float av = (kk == 0) ? a[i].x : (kk == 1) ? a[i].y
                          : (kk == 2) ? a[i].z : a[i].w;
                x[i][0] = fmaf(av, bv.x, x[i][0]);
                x[i][1] = fmaf(av, bv.y, x[i][1]);
                x[i][2] = fmaf(av, bv.z, x[i][2]);
                x[i][3] = fmaf(av, bv.w, x[i][3]);
            }
        }
    }
}

// ---------------- mma.sync plumbing ----------------
__device__ __forceinline__ uint32_t smem_u32(const void* p) {
    return (uint32_t)__cvta_generic_to_shared(p);
}
__device__ __forceinline__ void ldsm4(uint32_t r[4], uint32_t addr) {
    asm volatile("ldmatrix.sync.aligned.m8n8.x4.shared.b16 {%0,%1,%2,%3}, [%4];"
        : "=r"(r[0]), "=r"(r[1]), "=r"(r[2]), "=r"(r[3]) : "r"(addr));
}
__device__ __forceinline__ void ldsm4t(uint32_t r[4], uint32_t addr) {
    asm volatile("ldmatrix.sync.aligned.m8n8.x4.trans.shared.b16 {%0,%1,%2,%3}, [%4];"
        : "=r"(r[0]), "=r"(r[1]), "=r"(r[2]), "=r"(r[3]) : "r"(addr));
}
__device__ __forceinline__ void ldsm2t(uint32_t r[2], uint32_t addr) {
    asm volatile("ldmatrix.sync.aligned.m8n8.x2.trans.shared.b16 {%0,%1}, [%2];"
        : "=r"(r[0]), "=r"(r[1]) : "r"(addr));
}
__device__ __forceinline__ void mma16816(float c[4], const uint32_t a[4], const uint32_t b[2]) {
    asm volatile("mma.sync.aligned.m16n8k16.row.col.f32.bf16.bf16.f32 "
        "{%0,%1,%2,%3}, {%4,%5,%6,%7}, {%8,%9}, {%0,%1,%2,%3};"
        : "+f"(c[0]), "+f"(c[1]), "+f"(c[2]), "+f"(c[3])
        : "r"(a[0]), "r"(a[1]), "r"(a[2]), "r"(a[3]), "r"(b[0]), "r"(b[1]));
}

// 64x128 += A(64x128) * B(128x128 k-major), split-bf16 3-pass.
// warp covers rows 16*wr..+16, cols 64*wc..+64 (8 n-tiles).
__device__ __forceinline__ void mma_gemm64x128(
    const __nv_bfloat16* Ah, const __nv_bfloat16* Al,
    const __nv_bfloat16* Bh, const __nv_bfloat16* Bl,
    float acc[8][4], int wr, int wc, int l) {
    uint32_t aoff = (uint32_t)(((16*wr + (l & 15))*136 + ((l >> 4)*8)) * 2);
    uint32_t ah_base = smem_u32(Ah) + aoff;
    uint32_t al_base = smem_u32(Al) + aoff;
    uint32_t boff = (uint32_t)(((l & 15)*136 + 64*wc) * 2);
    uint32_t bh_base = smem_u32(Bh) + boff;
    uint32_t bl_base = smem_u32(Bl) + boff;
    #pragma unroll
    for (int kk = 0; kk < 8; kk++) {
        uint32_t a_h[4], a_l[4];
        ldsm4(a_h, ah_base + kk*32);
        ldsm4(a_l, al_base + kk*32);
        #pragma unroll
        for (int j = 0; j < 8; j++) {
            uint32_t b_h[2], b_l[2];
            ldsm2t(b_h, bh_base + kk*4352 + j*16);
            ldsm2t(b_l, bl_base + kk*4352 + j*16);
            mma16816(acc[j], a_h, b_h);
            mma16816(acc[j], a_h, b_l);
            mma16816(acc[j], a_l, b_h);
        }
    }
}

// load 64 fp32 rows -> bf16 hi/lo planes (stride 136 halves)
__device__ __forceinline__ void load_rows_bf16(const float* __restrict__ src,
                                               __nv_bfloat16* dh, __nv_bfloat16* dl, int t) {
    const float4* sp = (const float4*)src;
    #pragma unroll
    for (int it = 0; it < 8; it++) {
        int f = t + 256*it;             // 2048 float4
        int row = f >> 5, c4 = (f & 31) * 4;
        float4 v = sp[f];
        float vv[4] = {v.x, v.y, v.z, v.w};
        union { __nv_bfloat16 h[4]; uint2 u; } Hu, Lu;
        #pragma unroll
        for (int k = 0; k < 4; k++) bf16_split(vv[k], Hu.h[k], Lu.h[k]);
        *(uint2*)&dh[row*136 + c4] = Hu.u;
        *(uint2*)&dl[row*136 + c4] = Lu.u;
    }
}

// copy 128x128 bf16 global -> smem (stride 136 halves)
__device__ __forceinline__ void load_w_bf16(const __nv_bfloat16* __restrict__ src,
                                            __nv_bfloat16* dst, int t) {
    const uint4* sp = (const uint4*)src;   // 2048 uint4
    #pragma unroll
    for (int it = 0; it < 8; it++) {
        int u = t + 256*it;
        int row = u >> 4, c8 = (u & 15) * 8;
        *(uint4*)&dst[row*136 + c8] = sp[u];
    }
}

// =========================================================================
// Phase 1 (tensorized): T1[h] += phi(ks)^T * S ; kss[h] += sum phi(ks).
// grid = dim3(18, 8), 256 threads, smem SMEM_K1.
// =========================================================================
__global__ __launch_bounds__(256, 1) void k_phase1(const float* __restrict__ src,
                                                   const float* __restrict__ Wkb,
                                                   const float* __restrict__ nsc,
                                                   int nchunks) {
    extern __shared__ char smraw[];
    __nv_bfloat16* Sh = (__nv_bfloat16*)smraw;   // 64x136 source rows
    __nv_bfloat16* Sl = Sh + 64*136;
    __nv_bfloat16* Ph = Sl + 64*136;             // 64x136 phi
    __nv_bfloat16* Pl = Ph + 64*136;
    __nv_bfloat16* Bh = Pl + 64*136;             // 128x136 Wk planes
    __nv_bfloat16* Bl = Bh + 128*136;
    float* Xs = (float*)(Bl + 128*136);          // 64x132
    float* KB = Xs + 64*132;                     // 128 bias
    float* RS = KB + 128;                        // 64 row scales

    int t = threadIdx.x;
    int w = t >> 5, l = t & 31;
    int wrq = w & 3, wcq = w >> 2;   // qs gemm: 4 row-groups x 2 col-groups
    int m0 = w * 16;                 // T1 gemm: warp owns m-rows m0..m0+15
    int rr = t >> 2, g = t & 3;
    int h = blockIdx.y, slice = blockIdx.x;
    float inv = 1.f / (fabsf(*nsc) + 1e-6f);

    // Wk planes + bias: load once per block
    load_w_bf16(&g_Wk_h[h][0][0], Bh, t);
    load_w_bf16(&g_Wk_l[h][0][0], Bl, t);
    if (t < C) KB[t] = Wkb[h*C + t];

    // T1 accumulator: 16 n-tiles x 4 regs, register-resident across chunks
    float t1acc[16][4];
    #pragma unroll
    for (int j = 0; j < 16; j++)
        #pragma unroll
        for (int e = 0; e < 4; e++) t1acc[j][e] = 0.f;
    float kacc = 0.f;

    // A-trans base offsets for T1 (phi stored [row=k][m], need A[m][k])
    uint32_t at_off = (uint32_t)((((l & 7) + ((l >> 4) << 3))*136
                                  + m0 + (((l >> 3) & 1) << 3)) * 2);
    uint32_t pa_h = smem_u32(Ph) + at_off;
    uint32_t pa_l = smem_u32(Pl) + at_off;
    uint32_t bt_off = (uint32_t)(((l & 15)*136) * 2);
    uint32_t sb_h = smem_u32(Sh) + bt_off;
    uint32_t sb_l = smem_u32(Sl) + bt_off;

    for (int ch = slice; ch < nchunks; ch += 18) {
        __syncthreads();   // Bh/KB ready (1st iter); S/P free of prior-chunk readers
        load_rows_bf16(src + (size_t)ch*64*C, Sh, Sl, t);
        __syncthreads();

        // qs = S * Wk^T
        float x[8][4];
        #pragma unroll
        for (int j = 0; j < 8; j++)
            #pragma unroll
            for (int e = 0; e < 4; e++) x[j][e] = 0.f;
        mma_gemm64x128(Sh, Sl, Bh, Bl, x, wrq, wcq, l);
        int srow = 16*wrq + (l >> 2), scol = 64*wcq + 2*(l & 3);
        #pragma unroll
        for (int j = 0; j < 8; j++) {
            *(float2*)&Xs[srow*132 + scol + 8*j]     = make_float2(x[j][0], x[j][1]);
            *(float2*)&Xs[(srow+8)*132 + scol + 8*j] = make_float2(x[j][2], x[j][3]);
        }
        __syncthreads();

        // phi + row norms
        float s1 = 0.f, s2 = 0.f;
        #pragma unroll
        for (int cc = 0; cc < 32; cc++) {
            int col = g + 4*cc;
            float xv = Xs[rr*132 + col] + KB[col];
            float v = (fmaxf(xv, 0.f) + 1e-6f) * inv;
            float p = v * v;
            Xs[rr*132 + col] = p;
            s1 += p; s2 = fmaf(p, p, s2);
        }
        s1 += __shfl_xor_sync(0xffffffffu, s1, 1);
        s2 += __shfl_xor_sync(0xffffffffu, s2, 1);
        s1 += __shfl_xor_sync(0xffffffffu, s1, 2);
        s2 += __shfl_xor_sync(0xffffffffu, s2, 2);
        if (g == 0) RS[rr] = sqrtf(s1) / (sqrtf(s2) + 1e-8f);
        __syncthreads();

        // scale + split phi into Ph/Pl (and scaled fp32 back to Xs for kss)
        float sc = RS[rr];
        #pragma unroll
        for (int cc = 0; cc < 32; cc++) {
            int col = g + 4*cc;
            float val = Xs[rr*132 + col] * sc;
            Xs[rr*132 + col] = val;
            __nv_bfloat16 hi, lo;
            bf16_split(val, hi, lo);
            Ph[rr*136 + col] = hi;
            Pl[rr*136 + col] = lo;
        }
        __syncthreads();

        // kss column sums
        if (t < C) {
            float a = 0.f;
            #pragma unroll
            for (int rw = 0; rw < 64; rw++) a += Xs[rw*132 + t];
            kacc += a;
        }

        // T1 += phi^T * S   (A = phi trans, B = S planes; k = 64 rows)
        #pragma unroll
        for (int kk = 0; kk < 4; kk++) {
            uint32_t a_h[4], a_l[4];
            ldsm4t(a_h, pa_h + kk*4352);
            ldsm4t(a_l, pa_l + kk*4352);
            #pragma unroll
            for (int j = 0; j < 16; j++) {
                uint32_t b_h[2], b_l[2];
                ldsm2t(b_h, sb_h + kk*4352 + j*16);
                ldsm2t(b_l, sb_l + kk*4352 + j*16);
                mma16816(t1acc[j], a_h, b_h);
                mma16816(t1acc[j], a_h, b_l);
                mma16816(t1acc[j], a_l, b_h);
            }
        }
    }

    // flush T1 accumulator
    int mrow = m0 + (l >> 2), colb = 2*(l & 3);
    #pragma unroll
    for (int j = 0; j < 16; j++) {
        atomicAdd(&g_T1[h][mrow][8*j + colb],     t1acc[j][0]);
        atomicAdd(&g_T1[h][mrow][8*j + colb + 1], t1acc[j][1]);
        atomicAdd(&g_T1[h][mrow+8][8*j + colb],     t1acc[j][2]);
        atomicAdd(&g_T1[h][mrow+8][8*j + colb + 1], t1acc[j][3]);
    }
    if (t < C) atomicAdd(&g_kss[h][t], kacc);
}

// =========================================================================
// K2: ktv[h] = T1[h]*Wv_h^T + kss_h (x) Wv_b_h -> bf16 hi/lo planes [m][d].
// 16 blocks x 256, SMEM_K2.
// =========================================================================
__global__ __launch_bounds__(256, 1) void k_ktv(const float* __restrict__ Wvb) {
    extern __shared__ float sm[];
    float* T = sm;           // 64*128
    float* W = T + 8192;     // 128*128 WvT
    int b = blockIdx.x;
    int h = b >> 1, half = b & 1;
    int t = threadIdx.x, ty = t >> 5, tx = t & 31;
    #pragma unroll
    for (int it = 0; it < 8; it++)
        ((float4*)T)[t + 256*it] = ((const float4*)&g_T1[h][half*64][0])[t + 256*it];
    #pragma unroll
    for (int it = 0; it < 16; it++)
        ((float4*)W)[t + 256*it] = ((const float4*)&g_WvT[h][0][0])[t + 256*it];
    __syncthreads();
    float x[8][4];
    #pragma unroll
    for (int i = 0; i < 8; i++)
        #pragma unroll
        for (int j = 0; j < 4; j++) x[i][j] = 0.f;
    gemm_tile(T, W, ty, tx, x, C);
    float4 bb = *(const float4*)(Wvb + h*C + tx*4);
    #pragma unroll
    for (int i = 0; i < 8; i++) {
        int m = half*64 + ty*8 + i;
        float ks = g_kss[h][m];
        float o[4];
        o[0] = fmaf(ks, bb.x, x[i][0]);
        o[1] = fmaf(ks, bb.y, x[i][1]);
        o[2] = fmaf(ks, bb.z, x[i][2]);
        o[3] = fmaf(ks, bb.w, x[i][3]);
        #pragma unroll
        for (int j = 0; j < 4; j++) {
            __nv_bfloat16 hi, lo;
            bf16_split(o[j], hi, lo);
            g_ktv_h[h][m][tx*4 + j] = hi;
            g_ktv_l[h][m][tx*4 + j] = lo;
        }
    }
}

// =========================================================================
// Phase 2 (tensorized): vss + 8-head attention + heads mean + Lorentz time.
// N/64 blocks x 256 threads, smem SMEM_K3.
// =========================================================================
__global__ __launch_bounds__(256, 1) void k_phase2(const float* __restrict__ qin,
                                                   const float* __restrict__ sin_,
                                                   const float* __restrict__ Wqb,
                                                   const float* __restrict__ nsc,
                                                   float* __restrict__ out) {
    extern __shared__ char smraw[];
    __nv_bfloat16* Qh = (__nv_bfloat16*)smraw;
    __nv_bfloat16* Ql = Qh + 64*136;
    __nv_bfloat16* Ah = Ql + 64*136;
    __nv_bfloat16* Al = Ah + 64*136;
    __nv_bfloat16* Bh = Al + 64*136;
    __nv_bfloat16* Bl = Bh + 128*136;
    float* Xs = (float*)(Bl + 128*136);  // 64*132
    float* QB = Xs + 64*132;             // 128
    float* KS = QB + 128;                // 128
    float* WR = KS + 128;                // 64
    float* TS = WR + 64;                 // 64

    int t = threadIdx.x;
    int w = t >> 5, l = t & 31, wr = w >> 1, wc = w & 1;
    int rr = t >> 2, g = t & 3;
    int r0 = blockIdx.x * 64;
    float inv = 1.f / (fabsf(*nsc) + 1e-6f);
    int srow = 16*wr + (l >> 2), scol = 64*wc + 2*(l & 3);

    // ---- load Q, S (bf16 planes) and M weights ----
    load_rows_bf16(qin + (size_t)r0*C, Qh, Ql, t);
    load_rows_bf16(sin_ + (size_t)r0*C, Ah, Al, t);
    load_w_bf16(&g_M_h[0][0], Bh, t);
    load_w_bf16(&g_M_l[0][0], Bl, t);
    __syncthreads();

    // ---- acc = c + S*M^T (vss head-mean) ----
    float acc[8][4];
    #pragma unroll
    for (int j = 0; j < 8; j++) {
        float2 cv = *(const float2*)&g_c[64*wc + 8*j + 2*(l & 3)];
        acc[j][0] = cv.x; acc[j][1] = cv.y; acc[j][2] = cv.x; acc[j][3] = cv.y;
    }
    mma_gemm64x128(Ah, Al, Bh, Bl, acc, wr, wc, l);

    for (int h = 0; h < H; h++) {
        __syncthreads();  // prior mma (vss or num) done with Abuf/Bbuf
        load_w_bf16(&g_Wq_h[h][0][0], Bh, t);
        load_w_bf16(&g_Wq_l[h][0][0], Bl, t);
        if (t < 32)      ((float4*)QB)[t]    = ((const float4*)(Wqb + h*C))[t];
        else if (t < 64) ((float4*)KS)[t-32] = ((const float4*)&g_kss[h][0])[t-32];
        __syncthreads();

        // qs = Q * Wq^T
        float x[8][4];
        #pragma unroll
        for (int j = 0; j < 8; j++)
            #pragma unroll
            for (int e = 0; e < 4; e++) x[j][e] = 0.f;
        mma_gemm64x128(Qh, Ql, Bh, Bl, x, wr, wc, l);
        #pragma unroll
        for (int j = 0; j < 8; j++) {
            *(float2*)&Xs[srow*132 + scol + 8*j]     = make_float2(x[j][0], x[j][1]);
            *(float2*)&Xs[(srow+8)*132 + scol + 8*j] = make_float2(x[j][2], x[j][3]);
        }
        __syncthreads();

        // phi + row reductions; then stage ktv into B planes
        float s1 = 0.f, s2 = 0.f, s3 = 0.f;
        #pragma unroll
        for (int cc = 0; cc < 32; cc++) {
            int col = g + 4*cc;
            float xv = Xs[rr*132 + col] + QB[col];
            float v = (fmaxf(xv, 0.f) + 1e-6f) * inv;
            float p = v * v;
            Xs[rr*132 + col] = p;
            s1 += p; s2 = fmaf(p, p, s2); s3 = fmaf(p, KS[col], s3);
        }
        s1 += __shfl_xor_sync(0xffffffffu, s1, 1);
        s2 += __shfl_xor_sync(0xffffffffu, s2, 1);
        s3 += __shfl_xor_sync(0xffffffffu, s3, 1);
        s1 += __shfl_xor_sync(0xffffffffu, s1, 2);
        s2 += __shfl_xor_sync(0xffffffffu, s2, 2);
        s3 += __shfl_xor_sync(0xffffffffu, s3, 2);
        if (g == 0) {
            float scv = sqrtf(s1) / (sqrtf(s2) + 1e-8f);
            WR[rr] = scv / (8.f * fmaf(scv, s3, 1e-6f));
        }
        load_w_bf16(&g_ktv_h[h][0][0], Bh, t);
        load_w_bf16(&g_ktv_l[h][0][0], Bl, t);
        __syncthreads();

        // A = bf16(w_row * p)
        float wgt = WR[rr];
        #pragma unroll
        for (int cc = 0; cc < 32; cc++) {
            int col = g + 4*cc;
            float val = Xs[rr*132 + col] * wgt;
            __nv_bfloat16 hi, lo;
            bf16_split(val, hi, lo);
            Ah[rr*136 + col] = hi;
            Al[rr*136 + col] = lo;
        }
        __syncthreads();

        // acc += (w.p) * ktv
        mma_gemm64x128(Ah, Al, Bh, Bl, acc, wr, wc, l);
    }

    // ---- stage acc, Lorentz time coordinate, store ----
    __syncthreads();
    #pragma unroll
    for (int j = 0; j < 8; j++) {
        *(float2*)&Xs[srow*132 + scol + 8*j]     = make_float2(acc[j][0], acc[j][1]);
        *(float2*)&Xs[(srow+8)*132 + scol + 8*j] = make_float2(acc[j][2], acc[j][3]);
    }
    __syncthreads();
    float ssq = 0.f;
    #pragma unroll
    for (int cc = 0; cc < 32; cc++) {
        float pv = Xs[rr*132 + g + 4*cc];
        ssq = fmaf(pv, pv, ssq);
    }
    ssq += __shfl_xor_sync(0xffffffffu, ssq, 1);
    ssq += __shfl_xor_sync(0xffffffffu, ssq, 2);
    if (g == 0) TS[rr] = sqrtf(ssq + 1.0f);
    __syncthreads();
    {
        int row = r0 + rr;
        float* op = out + (size_t)row * 129;
        #pragma unroll
        for (int cc = 0; cc < 32; cc++) {
            int col = g + 4*cc;
            op[1 + col] = Xs[rr*132 + col];
        }
        if (g == 0) op[0] = TS[rr];
    }
}

// =========================================================================
extern "C" void kernel_launch(void* const* d_in, const int* in_sizes, int n_in,
                              void* d_out, int out_size) {
    const float* qin = (const float*)d_in[0];
    const float* sin_ = (const float*)d_in[1];
    const float* Wq  = (const float*)d_in[2];
    const float* Wqb = (const float*)d_in[3];
    const float* Wk  = (const float*)d_in[4];
    const float* Wkb = (const float*)d_in[5];
    const float* Wv  = (const float*)d_in[6];
    const float* Wvb = (const float*)d_in[7];
    const float* vmw = (const float*)d_in[8];
    const float* vmb = (const float*)d_in[9];
    const float* nsc = (const float*)d_in[10];
    float* out = (float*)d_out;
    int N = in_sizes[0] / C;
    int nchunks = N / 64;

    cudaFuncSetAttribute(k_prep2,  cudaFuncAttributeMaxDynamicSharedMemorySize, SMEM_P2);
    cudaFuncSetAttribute(k_phase1, cudaFuncAttributeMaxDynamicSharedMemorySize, SMEM_K1);
    cudaFuncSetAttribute(k_ktv,    cudaFuncAttributeMaxDynamicSharedMemorySize, SMEM_K2);
    cudaFuncSetAttribute(k_phase2, cudaFuncAttributeMaxDynamicSharedMemorySize, SMEM_K3);

    k_prep1<<<33, 256>>>(Wq, Wk, Wv, Wvb);
    k_prep2<<<4, 256, SMEM_P2>>>(vmw, vmb);
    k_phase1<<<dim3(18, H), 256, SMEM_K1>>>(sin_, Wkb, nsc, nchunks);
    k_ktv<<<16, 256, SMEM_K2>>>(Wvb);
    k_phase2<<<nchunks, 256, SMEM_K3>>>(qin, sin_, Wqb, nsc, out);
}

// round 17
// speedup vs baseline: 2.2450x; 1.2415x over previous
#include <cuda_runtime.h>
#include <cuda_bf16.h>
#include <cstdint>

constexpr int C = 128;
constexpr int H = 8;

// ---------------- device scratch (no allocation) ----------------
__device__ float g_WvT[H][C][C];            // [h][i][d] fp32 (k_ktv)
__device__ float g_T1 [H][C][C];            // phi(K)^T * S : [h][m][i]
__device__ float g_kss[H][C];               // sum_n phi_ks
__device__ float g_c  [C];                  // v_map bias term
__device__ float g_bva[C];
__device__ float g_Wva[C][C];               // mean_h Wv : [d][i]
// fragment-ordered weights: frag idx = ((wc*8+kk)*8+j)*32 + lane, uint2 = {b0,b1}
__device__ uint2 g_WkF_h[H][4096];
__device__ uint2 g_WkF_l[H][4096];
__device__ uint2 g_WqF_h[H][4096];
__device__ uint2 g_WqF_l[H][4096];
__device__ uint2 g_MF_h[4096];
__device__ uint2 g_MF_l[4096];
__device__ uint2 g_ktvF_h[H][4096];
__device__ uint2 g_ktvF_l[H][4096];

// phase1: Sh,Sl,Ph,Pl (64x136 bf16) + Xs(64x132 f32) + KB(128) + RS(64)
#define SMEM_K1 ((4*64*136) * 2 + (64*132 + 128 + 64) * 4)
#define SMEM_K2 ((8192 + 16384) * 4)
#define SMEM_P2 ((128*129 + 128*33) * 4)
// phase2: Qh,Ql,Ah,Al (64x136 bf16) + Xs (64x132 f32) + QB,KS,WR,TS
#define SMEM_K3 ((4*64*136) * 2 + (64*132 + 128 + 128 + 64 + 64) * 4)

// ---------------- bf16 helpers ----------------
__device__ __forceinline__ void bf16_split(float v, __nv_bfloat16& hi, __nv_bfloat16& lo) {
    hi = __float2bfloat16_rn(v);
    lo = __float2bfloat16_rn(v - __bfloat162float(hi));
}
__device__ __forceinline__ uint32_t bf16pack(__nv_bfloat16 a, __nv_bfloat16 b) {
    return ((uint32_t)__bfloat16_as_ushort(b) << 16) | (uint32_t)__bfloat16_as_ushort(a);
}
// fragment position for element (k, n) of a 128x128 k-major B matrix:
// half index within uint2-array = idx*4 + reg*2 + (k&1)
__device__ __forceinline__ int frag_half_index(int k, int n) {
    int wc = n >> 6, j = (n >> 3) & 7, kk = k >> 4;
    int lane = ((n & 7) << 2) | ((k & 7) >> 1);
    int idx = ((wc*8 + kk)*8 + j)*32 + lane;
    int reg = ((k & 15) < 8) ? 0 : 1;
    return idx*4 + reg*2 + (k & 1);
}

// =========================================================================
// Prep 1: Wk/Wq -> fragment-ordered bf16 hi/lo, Wv transpose (fp32),
// Wv average, zero accumulators. 33 blocks x 256.
// =========================================================================
__global__ void k_prep1(const float* __restrict__ Wq, const float* __restrict__ Wk,
                        const float* __restrict__ Wv, const float* __restrict__ Wvb) {
    int b = blockIdx.x, t = threadIdx.x;
    if (b < 16) {
        const float* src;
        uint2 *dh, *dl;
        if (b < 8) { src = Wk + b*C*C;      dh = g_WkF_h[b];   dl = g_WkF_l[b]; }
        else       { src = Wq + (b-8)*C*C;  dh = g_WqF_h[b-8]; dl = g_WqF_l[b-8]; }
        #pragma unroll
        for (int it = 0; it < 16; it++) {
            int f = t + 256*it;
            int l = f & 31, j = (f >> 5) & 7, kk = (f >> 8) & 7, wc = (f >> 11) & 1;
            int n  = wc*64 + j*8 + (l >> 2);
            int K0 = kk*16 + (l & 3)*2;
            float w00 = src[n*C + K0];
            float w01 = src[n*C + K0 + 1];
            float w10 = src[n*C + K0 + 8];
            float w11 = src[n*C + K0 + 9];
            __nv_bfloat16 h00,l00,h01,l01,h10,l10,h11,l11;
            bf16_split(w00, h00, l00); bf16_split(w01, h01, l01);
            bf16_split(w10, h10, l10); bf16_split(w11, h11, l11);
            dh[f] = make_uint2(bf16pack(h00, h01), bf16pack(h10, h11));
            dl[f] = make_uint2(bf16pack(l00, l01), bf16pack(l10, l11));
        }
    } else if (b < 24) {
        const float* src = Wv + (b-16)*C*C;
        float* dst = &g_WvT[b-16][0][0];
        #pragma unroll
        for (int it = 0; it < 16; it++) {
            int f = t + 256*it;
            int o = f >> 5, i = (f & 31) * 4;
            float4 v = *(const float4*)(src + o*C + i);
            dst[(i+0)*C + o] = v.x;
            dst[(i+1)*C + o] = v.y;
            dst[(i+2)*C + o] = v.z;
            dst[(i+3)*C + o] = v.w;
        }
    } else if (b == 24) {
        for (int it = 0; it < 64; it++) {
            int idx = t + 256*it;
            float a = 0.f;
            #pragma unroll
            for (int h = 0; h < H; h++) a += Wv[h*C*C + idx];
            (&g_Wva[0][0])[idx] = a * 0.125f;
        }
        if (t < C) {
            float a = 0.f;
            #pragma unroll
            for (int h = 0; h < H; h++) a += Wvb[h*C + t];
            g_bva[t] = a * 0.125f;
        }
    } else {
        int zb = b - 25;  // 0..7
        float4* T4 = (float4*)&g_T1[0][0][0];
        #pragma unroll
        for (int it = 0; it < 16; it++)
            T4[zb*256 + t + 2048*it] = make_float4(0.f, 0.f, 0.f, 0.f);
        if (zb == 0)
            ((float4*)&g_kss[0][0])[t] = make_float4(0.f, 0.f, 0.f, 0.f);
    }
}

// =========================================================================
// Prep 2: M = v_map_w * Wv_avg -> fragment-ordered bf16; c vector. 4 blocks.
// =========================================================================
__global__ void k_prep2(const float* __restrict__ vmw, const float* __restrict__ vmb) {
    extern __shared__ float sm[];
    float* VS = sm;             // [128][129] vmw
    float* AS = VS + 128*129;   // [128][33]  Wva slice
    int b = blockIdx.x, t = threadIdx.x;
    int i0 = b * 32;
    #pragma unroll
    for (int it = 0; it < 16; it++) {
        int f = t + 256*it; int o = f >> 5, d4 = (f & 31) * 4;
        float4 v = *(const float4*)(vmw + o*C + d4);
        VS[o*129 + d4+0] = v.x; VS[o*129 + d4+1] = v.y;
        VS[o*129 + d4+2] = v.z; VS[o*129 + d4+3] = v.w;
    }
    #pragma unroll
    for (int it = 0; it < 16; it++) {
        int f = t + 256*it;
        int d = f >> 5, ii = f & 31;
        AS[d*33 + ii] = g_Wva[d][i0 + ii];
    }
    __syncthreads();
    int il = (t >> 4) * 2, o0 = (t & 15) * 8;
    float acc[2][8];
    #pragma unroll
    for (int i = 0; i < 2; i++)
        #pragma unroll
        for (int j = 0; j < 8; j++) acc[i][j] = 0.f;
    for (int d = 0; d < C; d++) {
        float a0 = AS[d*33 + il], a1 = AS[d*33 + il + 1];
        #pragma unroll
        for (int j = 0; j < 8; j++) {
            float bv = VS[(o0+j)*129 + d];
            acc[0][j] = fmaf(a0, bv, acc[0][j]);
            acc[1][j] = fmaf(a1, bv, acc[1][j]);
        }
    }
    __nv_bfloat16* MH = (__nv_bfloat16*)g_MF_h;
    __nv_bfloat16* ML = (__nv_bfloat16*)g_MF_l;
    #pragma unroll
    for (int i = 0; i < 2; i++)
        #pragma unroll
        for (int j = 0; j < 8; j++) {
            __nv_bfloat16 hi, lo;
            bf16_split(acc[i][j], hi, lo);
            int hidx = frag_half_index(i0 + il + i, o0 + j);
            MH[hidx] = hi;
            ML[hidx] = lo;
        }
    if (b == 0) {
        __syncthreads();
        if (t < C) {
            float a = 0.f;
            for (int d = 0; d < C; d++) a = fmaf(VS[t*129 + d], g_bva[d], a);
            g_c[t] = a + vmb[t];
        }
    }
}

// ---- fp32 tile GEMM (k_ktv): X += A(64 x 128) * B(128 x 128, k-major) ----
__device__ __forceinline__ void gemm_tile(const float* __restrict__ A,
                                          const float* __restrict__ B,
                                          int ty, int tx, float x[8][4], int astride) {
    for (int k4 = 0; k4 < 32; k4++) {
        float4 a[8];
        #pragma unroll
        for (int i = 0; i < 8; i++)
            a[i] = *(const float4*)&A[(ty*8 + i)*astride + k4*4];
        #pragma unroll
        for (int kk = 0; kk < 4; kk++) {
            float4 bv = *(const float4*)&B[(k4*4 + kk)*C + tx*4];
            #pragma unroll
            for (int i = 0; i < 8; i++) {
                float av = (kk == 0) ? a[i].x : (kk == 1) ? a[i].y
                          : (kk == 2) ? a[i].z : a[i].w;
                x[i][0] = fmaf(av, bv.x, x[i][0]);
                x[i][1] = fmaf(av, bv.y, x[i][1]);
                x[i][2] = fmaf(av, bv.z, x[i][2]);
                x[i][3] = fmaf(av, bv.w, x[i][3]);
            }
        }
    }
}

// ---------------- mma.sync plumbing ----------------
__device__ __forceinline__ uint32_t smem_u32(const void* p) {
    return (uint32_t)__cvta_generic_to_shared(p);
}
__device__ __forceinline__ void ldsm4(uint32_t r[4], uint32_t addr) {
    asm volatile("ldmatrix.sync.aligned.m8n8.x4.shared.b16 {%0,%1,%2,%3}, [%4];"
        : "=r"(r[0]), "=r"(r[1]), "=r"(r[2]), "=r"(r[3]) : "r"(addr));
}
__device__ __forceinline__ void ldsm4t(uint32_t r[4], uint32_t addr) {
    asm volatile("ldmatrix.sync.aligned.m8n8.x4.trans.shared.b16 {%0,%1,%2,%3}, [%4];"
        : "=r"(r[0]), "=r"(r[1]), "=r"(r[2]), "=r"(r[3]) : "r"(addr));
}
__device__ __forceinline__ void ldsm2t(uint32_t r[2], uint32_t addr) {
    asm volatile("ldmatrix.sync.aligned.m8n8.x2.trans.shared.b16 {%0,%1}, [%2];"
        : "=r"(r[0]), "=r"(r[1]) : "r"(addr));
}
__device__ __forceinline__ void mma16816(float c[4], const uint32_t a[4], const uint32_t b[2]) {
    asm volatile("mma.sync.aligned.m16n8k16.row.col.f32.bf16.bf16.f32 "
        "{%0,%1,%2,%3}, {%4,%5,%6,%7}, {%8,%9}, {%0,%1,%2,%3};"
        : "+f"(c[0]), "+f"(c[1]), "+f"(c[2]), "+f"(c[3])
        : "r"(a[0]), "r"(a[1]), "r"(a[2]), "r"(a[3]), "r"(b[0]), "r"(b[1]));
}

// 64x128 += A(64x128 smem planes) * B(global fragment-ordered), split-bf16 3-pass.
// warp covers rows 16*wr..+16, cols 64*wc..+64.
__device__ __forceinline__ void mma_gemm64x128_gb(
    const __nv_bfloat16* Ah, const __nv_bfloat16* Al,
    const uint2* __restrict__ BFh, const uint2* __restrict__ BFl,
    float acc[8][4], int wr, int wc, int l) {
    uint32_t aoff = (uint32_t)(((16*wr + (l & 15))*136 + ((l >> 4)*8)) * 2);
    uint32_t ah_base = smem_u32(Ah) + aoff;
    uint32_t al_base = smem_u32(Al) + aoff;
    const uint2* bh = BFh + (wc << 11) + l;
    const uint2* bl = BFl + (wc << 11) + l;
    #pragma unroll
    for (int kk = 0; kk < 8; kk++) {
        uint32_t a_h[4], a_l[4];
        ldsm4(a_h, ah_base + kk*32);
        ldsm4(a_l, al_base + kk*32);
        #pragma unroll
        for (int j = 0; j < 8; j++) {
            uint2 vh = __ldg(bh + kk*256 + j*32);
            uint2 vl = __ldg(bl + kk*256 + j*32);
            uint32_t bhp[2] = {vh.x, vh.y};
            uint32_t blp[2] = {vl.x, vl.y};
            mma16816(acc[j], a_h, bhp);
            mma16816(acc[j], a_h, blp);
            mma16816(acc[j], a_l, bhp);
        }
    }
}

// load 64 fp32 rows -> bf16 hi/lo planes (stride 136 halves)
__device__ __forceinline__ void load_rows_bf16(const float* __restrict__ src,
                                               __nv_bfloat16* dh, __nv_bfloat16* dl, int t) {
    const float4* sp = (const float4*)src;
    #pragma unroll
    for (int it = 0; it < 8; it++) {
        int f = t + 256*it;             // 2048 float4
        int row = f >> 5, c4 = (f & 31) * 4;
        float4 v = sp[f];
        float vv[4] = {v.x, v.y, v.z, v.w};
        union { __nv_bfloat16 h[4]; uint2 u; } Hu, Lu;
        #pragma unroll
        for (int k = 0; k < 4; k++) bf16_split(vv[k], Hu.h[k], Lu.h[k]);
        *(uint2*)&dh[row*136 + c4] = Hu.u;
        *(uint2*)&dl[row*136 + c4] = Lu.u;
    }
}

// =========================================================================
// Phase 1 (tensorized): T1[h] += phi(ks)^T * S ; kss[h] += sum phi(ks).
// grid = dim3(36, 8), 256 threads, smem SMEM_K1, 2 CTAs/SM.
// =========================================================================
__global__ __launch_bounds__(256, 2) void k_phase1(const float* __restrict__ src,
                                                   const float* __restrict__ Wkb,
                                                   const float* __restrict__ nsc,
                                                   int nchunks) {
    extern __shared__ char smraw[];
    __nv_bfloat16* Sh = (__nv_bfloat16*)smraw;   // 64x136 source rows
    __nv_bfloat16* Sl = Sh + 64*136;
    __nv_bfloat16* Ph = Sl + 64*136;             // 64x136 phi
    __nv_bfloat16* Pl = Ph + 64*136;
    float* Xs = (float*)(Pl + 64*136);           // 64x132
    float* KB = Xs + 64*132;                     // 128 bias
    float* RS = KB + 128;                        // 64 row scales

    int t = threadIdx.x;
    int w = t >> 5, l = t & 31;
    int wrq = w & 3, wcq = w >> 2;   // qs gemm: 4 row-groups x 2 col-groups
    int m0 = w * 16;                 // T1 gemm: warp owns m-rows m0..m0+15
    int rr = t >> 2, g = t & 3;
    int h = blockIdx.y, slice = blockIdx.x;
    float inv = 1.f / (fabsf(*nsc) + 1e-6f);
    const uint2* WkFh = g_WkF_h[h];
    const uint2* WkFl = g_WkF_l[h];

    if (t < C) KB[t] = Wkb[h*C + t];

    // T1 accumulator: 16 n-tiles x 4 regs, register-resident across chunks
    float t1acc[16][4];
    #pragma unroll
    for (int j = 0; j < 16; j++)
        #pragma unroll
        for (int e = 0; e < 4; e++) t1acc[j][e] = 0.f;
    float kacc = 0.f;

    // A-trans base offsets for T1 (phi stored [row=k][m], need A[m][k])
    uint32_t at_off = (uint32_t)((((l & 7) + ((l >> 4) << 3))*136
                                  + m0 + (((l >> 3) & 1) << 3)) * 2);
    uint32_t pa_h = smem_u32(Ph) + at_off;
    uint32_t pa_l = smem_u32(Pl) + at_off;
    uint32_t bt_off = (uint32_t)(((l & 15)*136) * 2);
    uint32_t sb_h = smem_u32(Sh) + bt_off;
    uint32_t sb_l = smem_u32(Sl) + bt_off;

    for (int ch = slice; ch < nchunks; ch += 36) {
        __syncthreads();   // KB ready (1st iter); S/P free of prior-chunk readers
        load_rows_bf16(src + (size_t)ch*64*C, Sh, Sl, t);
        __syncthreads();

        // qs = S * Wk^T   (B from global fragments)
        float x[8][4];
        #pragma unroll
        for (int j = 0; j < 8; j++)
            #pragma unroll
            for (int e = 0; e < 4; e++) x[j][e] = 0.f;
        mma_gemm64x128_gb(Sh, Sl, WkFh, WkFl, x, wrq, wcq, l);
        int srow = 16*wrq + (l >> 2), scol = 64*wcq + 2*(l & 3);
        #pragma unroll
        for (int j = 0; j < 8; j++) {
            *(float2*)&Xs[srow*132 + scol + 8*j]     = make_float2(x[j][0], x[j][1]);
            *(float2*)&Xs[(srow+8)*132 + scol + 8*j] = make_float2(x[j][2], x[j][3]);
        }
        __syncthreads();

        // phi + row norms
        float s1 = 0.f, s2 = 0.f;
        #pragma unroll
        for (int cc = 0; cc < 32; cc++) {
            int col = g + 4*cc;
            float xv = Xs[rr*132 + col] + KB[col];
            float v = (fmaxf(xv, 0.f) + 1e-6f) * inv;
            float p = v * v;
            Xs[rr*132 + col] = p;
            s1 += p; s2 = fmaf(p, p, s2);
        }
        s1 += __shfl_xor_sync(0xffffffffu, s1, 1);
        s2 += __shfl_xor_sync(0xffffffffu, s2, 1);
        s1 += __shfl_xor_sync(0xffffffffu, s1, 2);
        s2 += __shfl_xor_sync(0xffffffffu, s2, 2);
        if (g == 0) RS[rr] = sqrtf(s1) / (sqrtf(s2) + 1e-8f);
        __syncthreads();

        // scale + split phi into Ph/Pl (and scaled fp32 back to Xs for kss)
        float sc = RS[rr];
        #pragma unroll
        for (int cc = 0; cc < 32; cc++) {
            int col = g + 4*cc;
            float val = Xs[rr*132 + col] * sc;
            Xs[rr*132 + col] = val;
            __nv_bfloat16 hi, lo;
            bf16_split(val, hi, lo);
            Ph[rr*136 + col] = hi;
            Pl[rr*136 + col] = lo;
        }
        __syncthreads();

        // kss column sums
        if (t < C) {
            float a = 0.f;
            #pragma unroll
            for (int rw = 0; rw < 64; rw++) a += Xs[rw*132 + t];
            kacc += a;
        }

        // T1 += phi^T * S   (A = phi trans, B = S planes; k = 64 rows)
        #pragma unroll
        for (int kk = 0; kk < 4; kk++) {
            uint32_t a_h[4], a_l[4];
            ldsm4t(a_h, pa_h + kk*4352);
            ldsm4t(a_l, pa_l + kk*4352);
            #pragma unroll
            for (int j = 0; j < 16; j++) {
                uint32_t b_h[2], b_l[2];
                ldsm2t(b_h, sb_h + kk*4352 + j*16);
                ldsm2t(b_l, sb_l + kk*4352 + j*16);
                mma16816(t1acc[j], a_h, b_h);
                mma16816(t1acc[j], a_h, b_l);
                mma16816(t1acc[j], a_l, b_h);
            }
        }
    }

    // flush T1 accumulator
    int mrow = m0 + (l >> 2), colb = 2*(l & 3);
    #pragma unroll
    for (int j = 0; j < 16; j++) {
        atomicAdd(&g_T1[h][mrow][8*j + colb],     t1acc[j][0]);
        atomicAdd(&g_T1[h][mrow][8*j + colb + 1], t1acc[j][1]);
        atomicAdd(&g_T1[h][mrow+8][8*j + colb],     t1acc[j][2]);
        atomicAdd(&g_T1[h][mrow+8][8*j + colb + 1], t1acc[j][3]);
    }
    if (t < C) atomicAdd(&g_kss[h][t], kacc);
}

// =========================================================================
// K2: ktv[h] = T1[h]*Wv_h^T + kss_h (x) Wv_b_h -> fragment-ordered bf16.
// 16 blocks x 256, SMEM_K2.
// =========================================================================
__global__ __launch_bounds__(256, 1) void k_ktv(const float* __restrict__ Wvb) {
    extern __shared__ float sm[];
    float* T = sm;           // 64*128
    float* W = T + 8192;     // 128*128 WvT
    int b = blockIdx.x;
    int h = b >> 1, half = b & 1;
    int t = threadIdx.x, ty = t >> 5, tx = t & 31;
    #pragma unroll
    for (int it = 0; it < 8; it++)
        ((float4*)T)[t + 256*it] = ((const float4*)&g_T1[h][half*64][0])[t + 256*it];
    #pragma unroll
    for (int it = 0; it < 16; it++)
        ((float4*)W)[t + 256*it] = ((const float4*)&g_WvT[h][0][0])[t + 256*it];
    __syncthreads();
    float x[8][4];
    #pragma unroll
    for (int i = 0; i < 8; i++)
        #pragma unroll
        for (int j = 0; j < 4; j++) x[i][j] = 0.f;
    gemm_tile(T, W, ty, tx, x, C);
    float4 bb = *(const float4*)(Wvb + h*C + tx*4);
    __nv_bfloat16* KH = (__nv_bfloat16*)g_ktvF_h[h];
    __nv_bfloat16* KL = (__nv_bfloat16*)g_ktvF_l[h];
    #pragma unroll
    for (int i = 0; i < 8; i++) {
        int m = half*64 + ty*8 + i;
        float ks = g_kss[h][m];
        float o[4];
        o[0] = fmaf(ks, bb.x, x[i][0]);
        o[1] = fmaf(ks, bb.y, x[i][1]);
        o[2] = fmaf(ks, bb.z, x[i][2]);
        o[3] = fmaf(ks, bb.w, x[i][3]);
        #pragma unroll
        for (int j = 0; j < 4; j++) {
            __nv_bfloat16 hi, lo;
            bf16_split(o[j], hi, lo);
            int hidx = frag_half_index(m, tx*4 + j);
            KH[hidx] = hi;
            KL[hidx] = lo;
        }
    }
}

// =========================================================================
// Phase 2 (tensorized): vss + 8-head attention + heads mean + Lorentz time.
// N/64 blocks x 256 threads, smem SMEM_K3, 2 CTAs/SM.
// =========================================================================
__global__ __launch_bounds__(256, 2) void k_phase2(const float* __restrict__ qin,
                                                   const float* __restrict__ sin_,
                                                   const float* __restrict__ Wqb,
                                                   const float* __restrict__ nsc,
                                                   float* __restrict__ out) {
    extern __shared__ char smraw[];
    __nv_bfloat16* Qh = (__nv_bfloat16*)smraw;
    __nv_bfloat16* Ql = Qh + 64*136;
    __nv_bfloat16* Ah = Ql + 64*136;
    __nv_bfloat16* Al = Ah + 64*136;
    float* Xs = (float*)(Al + 64*136);   // 64*132
    float* QB = Xs + 64*132;             // 128
    float* KS = QB + 128;                // 128
    float* WR = KS + 128;                // 64
    float* TS = WR + 64;                 // 64

    int t = threadIdx.x;
    int w = t >> 5, l = t & 31, wr = w >> 1, wc = w & 1;
    int rr = t >> 2, g = t & 3;
    int r0 = blockIdx.x * 64;
    float inv = 1.f / (fabsf(*nsc) + 1e-6f);
    int srow = 16*wr + (l >> 2), scol = 64*wc + 2*(l & 3);

    // ---- load Q, S (bf16 planes) ----
    load_rows_bf16(qin + (size_t)r0*C, Qh, Ql, t);
    load_rows_bf16(sin_ + (size_t)r0*C, Ah, Al, t);
    __syncthreads();

    // ---- acc = c + S*M^T (vss head-mean) ----
    float acc[8][4];
    #pragma unroll
    for (int j = 0; j < 8; j++) {
        float2 cv = *(const float2*)&g_c[64*wc + 8*j + 2*(l & 3)];
        acc[j][0] = cv.x; acc[j][1] = cv.y; acc[j][2] = cv.x; acc[j][3] = cv.y;
    }
    mma_gemm64x128_gb(Ah, Al, g_MF_h, g_MF_l, acc, wr, wc, l);

    for (int h = 0; h < H; h++) {
        // stage small per-head vectors (read after the sync below)
        if (t < 32)      ((float4*)QB)[t]    = ((const float4*)(Wqb + h*C))[t];
        else if (t < 64) ((float4*)KS)[t-32] = ((const float4*)&g_kss[h][0])[t-32];

        // qs = Q * Wq^T  (B from global fragments)
        float x[8][4];
        #pragma unroll
        for (int j = 0; j < 8; j++)
            #pragma unroll
            for (int e = 0; e < 4; e++) x[j][e] = 0.f;
        mma_gemm64x128_gb(Qh, Ql, g_WqF_h[h], g_WqF_l[h], x, wr, wc, l);
        #pragma unroll
        for (int j = 0; j < 8; j++) {
            *(float2*)&Xs[srow*132 + scol + 8*j]     = make_float2(x[j][0], x[j][1]);
            *(float2*)&Xs[(srow+8)*132 + scol + 8*j] = make_float2(x[j][2], x[j][3]);
        }
        __syncthreads();

        // phi + row reductions
        float s1 = 0.f, s2 = 0.f, s3 = 0.f;
        #pragma unroll
        for (int cc = 0; cc < 32; cc++) {
            int col = g + 4*cc;
            float xv = Xs[rr*132 + col] + QB[col];
            float v = (fmaxf(xv, 0.f) + 1e-6f) * inv;
            float p = v * v;
            Xs[rr*132 + col] = p;
            s1 += p; s2 = fmaf(p, p, s2); s3 = fmaf(p, KS[col], s3);
        }
        s1 += __shfl_xor_sync(0xffffffffu, s1, 1);
        s2 += __shfl_xor_sync(0xffffffffu, s2, 1);
        s3 += __shfl_xor_sync(0xffffffffu, s3, 1);
        s1 += __shfl_xor_sync(0xffffffffu, s1, 2);
        s2 += __shfl_xor_sync(0xffffffffu, s2, 2);
        s3 += __shfl_xor_sync(0xffffffffu, s3, 2);
        if (g == 0) {
            float scv = sqrtf(s1) / (sqrtf(s2) + 1e-8f);
            WR[rr] = scv / (8.f * fmaf(scv, s3, 1e-6f));
        }
        __syncthreads();

        // A = bf16(w_row * p)
        float wgt = WR[rr];
        #pragma unroll
        for (int cc = 0; cc < 32; cc++) {
            int col = g + 4*cc;
            float val = Xs[rr*132 + col] * wgt;
            __nv_bfloat16 hi, lo;
            bf16_split(val, hi, lo);
            Ah[rr*136 + col] = hi;
            Al[rr*136 + col] = lo;
        }
        __syncthreads();

        // acc += (w.p) * ktv  (B from global fragments)
        mma_gemm64x128_gb(Ah, Al, g_ktvF_h[h], g_ktvF_l[h], acc, wr, wc, l);
    }

    // ---- stage acc, Lorentz time coordinate, store ----
    __syncthreads();
    #pragma unroll
    for (int j = 0; j < 8; j++) {
        *(float2*)&Xs[srow*132 + scol + 8*j]     = make_float2(acc[j][0], acc[j][1]);
        *(float2*)&Xs[(srow+8)*132 + scol + 8*j] = make_float2(acc[j][2], acc[j][3]);
    }
    __syncthreads();
    float ssq = 0.f;
    #pragma unroll
    for (int cc = 0; cc < 32; cc++) {
        float pv = Xs[rr*132 + g + 4*cc];
        ssq = fmaf(pv, pv, ssq);
    }
    ssq += __shfl_xor_sync(0xffffffffu, ssq, 1);
    ssq += __shfl_xor_sync(0xffffffffu, ssq, 2);
    if (g == 0) TS[rr] = sqrtf(ssq + 1.0f);
    __syncthreads();
    {
        int row = r0 + rr;
        float* op = out + (size_t)row * 129;
        #pragma unroll
        for (int cc = 0; cc < 32; cc++) {
            int col = g + 4*cc;
            op[1 + col] = Xs[rr*132 + col];
        }
        if (g == 0) op[0] = TS[rr];
    }
}

// =========================================================================
extern "C" void kernel_launch(void* const* d_in, const int* in_sizes, int n_in,
                              void* d_out, int out_size) {
    const float* qin = (const float*)d_in[0];
    const float* sin_ = (const float*)d_in[1];
    const float* Wq  = (const float*)d_in[2];
    const float* Wqb = (const float*)d_in[3];
    const float* Wk  = (const float*)d_in[4];
    const float* Wkb = (const float*)d_in[5];
    const float* Wv  = (const float*)d_in[6];
    const float* Wvb = (const float*)d_in[7];
    const float* vmw = (const float*)d_in[8];
    const float* vmb = (const float*)d_in[9];
    const float* nsc = (const float*)d_in[10];
    float* out = (float*)d_out;
    int N = in_sizes[0] / C;
    int nchunks = N / 64;

    cudaFuncSetAttribute(k_prep2,  cudaFuncAttributeMaxDynamicSharedMemorySize, SMEM_P2);
    cudaFuncSetAttribute(k_phase1, cudaFuncAttributeMaxDynamicSharedMemorySize, SMEM_K1);
    cudaFuncSetAttribute(k_ktv,    cudaFuncAttributeMaxDynamicSharedMemorySize, SMEM_K2);
    cudaFuncSetAttribute(k_phase2, cudaFuncAttributeMaxDynamicSharedMemorySize, SMEM_K3);

    k_prep1<<<33, 256>>>(Wq, Wk, Wv, Wvb);
    k_prep2<<<4, 256, SMEM_P2>>>(vmw, vmb);
    k_phase1<<<dim3(36, H), 256, SMEM_K1>>>(sin_, Wkb, nsc, nchunks);
    k_ktv<<<16, 256, SMEM_K2>>>(Wvb);
    k_phase2<<<nchunks, 256, SMEM_K3>>>(qin, sin_, Wqb, nsc, out);
}